// round 2
// baseline (speedup 1.0000x reference)
#include <cuda_runtime.h>
#include <math.h>

#define NHEADS 8
#define NSAMP 4

// ---------------- scratch (static device globals; no allocation) ----------------
// pfeat: per-level projected features, layout [level][b][y][x][32ch]
//   L0: 4*128*128*32 = 2097152   off 0
//   L1: 4* 64* 64*32 =  524288   off 2097152
//   L2: 4* 32* 32*32 =  131072   off 2621440
//   L3: 4* 16* 16*32 =   32768   off 2752512
//   L4: 4* 16* 16*32 =   32768   off 2785280
static __device__ __align__(16) float g_pfeat[2818048];
static __device__ __align__(16) float g_h2[20480 * 256];
static __device__ __align__(16) float g_mlp[20480 * 512];

// ---------------- feature projection: pfeat[pix][j] = sum_c feat[b,c,pix]*W[c,j] + b[j] ----------------
__global__ void proj_kernel(const float* __restrict__ feat,
                            const float* __restrict__ Wp,
                            const float* __restrict__ bp,
                            int C, int HW, int outOff) {
    __shared__ float Wsh[64 * 32];
    int pix = blockIdx.x * blockDim.x + threadIdx.x;   // grid sized exactly to 4*HW
    int b = pix / HW;
    int idx = pix - b * HW;
    const float* fbase = feat + (size_t)b * C * HW + idx;

    float acc[32];
#pragma unroll
    for (int j = 0; j < 32; j++) acc[j] = bp[j];

    for (int c0 = 0; c0 < C; c0 += 64) {
        __syncthreads();
        for (int i = threadIdx.x; i < 64 * 32; i += blockDim.x)
            Wsh[i] = Wp[c0 * 32 + i];
        __syncthreads();
#pragma unroll 4
        for (int cc = 0; cc < 64; cc++) {
            float v = __ldg(fbase + (size_t)(c0 + cc) * HW);
            const float* wr = &Wsh[cc * 32];
#pragma unroll
            for (int j = 0; j < 32; j++) acc[j] = fmaf(v, wr[j], acc[j]);
        }
    }
    float* o = g_pfeat + outOff + (size_t)pix * 32;
#pragma unroll
    for (int j = 0; j < 32; j += 4)
        *(float4*)(o + j) = make_float4(acc[j], acc[j + 1], acc[j + 2], acc[j + 3]);
}

// ---------------- copy x0 token slice to output ----------------
__global__ void copy_x0_kernel(const float* __restrict__ x, float* __restrict__ out) {
    int i = blockIdx.x * blockDim.x + threadIdx.x;   // 262144 float4s total
    int b = i >> 16;              // 65536 float4 per batch of x0 slice
    int r = i & 65535;
    const float4* xi = (const float4*)x;
    float4* oo = (float4*)out;
    size_t off = (size_t)b * (6 * 65536) + r;        // (b,0,:,:) block
    oo[off] = xi[off];
}

// ---------------- block reduction helper (256 threads) ----------------
__device__ __forceinline__ float block_sum_256(float v, float* red) {
#pragma unroll
    for (int o = 16; o > 0; o >>= 1) v += __shfl_xor_sync(0xffffffffu, v, o);
    __syncthreads();
    if ((threadIdx.x & 31) == 0) red[threadIdx.x >> 5] = v;
    __syncthreads();
    return red[0] + red[1] + red[2] + red[3] + red[4] + red[5] + red[6] + red[7];
}

// ---------------- fused per-token kernel ----------------
// LN1 -> attn-weight/offset heads -> softmax/tanh -> bilinear sample of pfeat
// -> head combine -> +residual (write d_out) -> LN2 (write g_h2)
__global__ void token_kernel(const float* __restrict__ x,
                             const float* __restrict__ ref,
                             const float* __restrict__ n1g, const float* __restrict__ n1b,
                             const float* __restrict__ awW, const float* __restrict__ awb,
                             const float* __restrict__ soW, const float* __restrict__ sob,
                             const float* __restrict__ n2g, const float* __restrict__ n2b,
                             float* __restrict__ out) {
    __shared__ float h_sh[256];
    __shared__ float logit_sh[96];
    __shared__ float aw_sh[32];
    __shared__ float pos_sh[64];
    __shared__ __align__(16) float samp_sh[32 * 32];
    __shared__ float red[8];

    int m = blockIdx.x;          // token id: b*5120 + l*1024 + p
    int t = threadIdx.x;
    int b = m / 5120;
    int lp = m - b * 5120;
    int l = lp >> 10;
    int p = lp & 1023;

    size_t xq_off = ((size_t)(b * 6 + l + 1) * 1024 + p) * 256;
    size_t x0_off = ((size_t)(b * 6) * 1024 + p) * 256;

    float xqv = x[xq_off + t];
    float sv = xqv + x[x0_off + t];

    // LN1
    float mean = block_sum_256(sv, red) * (1.0f / 256.0f);
    float d = sv - mean;
    float var = block_sum_256(d * d, red) * (1.0f / 256.0f);
    float h = d * rsqrtf(var + 1e-5f) * n1g[t] + n1b[t];
    h_sh[t] = h;
    __syncthreads();

    // attention-weight logits (32) + sampling-offset logits (64)
    if (t < 96) {
        float acc;
        if (t < 32) {
            acc = awb[t];
#pragma unroll 4
            for (int k = 0; k < 256; k++) acc = fmaf(h_sh[k], __ldg(awW + k * 32 + t), acc);
        } else {
            int j = t - 32;
            acc = sob[j];
#pragma unroll 4
            for (int k = 0; k < 256; k++) acc = fmaf(h_sh[k], __ldg(soW + k * 64 + j), acc);
        }
        logit_sh[t] = acc;
    }
    __syncthreads();

    // softmax over NS=4 per head
    if (t < 8) {
        float v0 = logit_sh[t * 4 + 0], v1 = logit_sh[t * 4 + 1];
        float v2 = logit_sh[t * 4 + 2], v3 = logit_sh[t * 4 + 3];
        float mx = fmaxf(fmaxf(v0, v1), fmaxf(v2, v3));
        float e0 = expf(v0 - mx), e1 = expf(v1 - mx), e2 = expf(v2 - mx), e3 = expf(v3 - mx);
        float inv = 1.0f / (e0 + e1 + e2 + e3);
        aw_sh[t * 4 + 0] = e0 * inv;
        aw_sh[t * 4 + 1] = e1 * inv;
        aw_sh[t * 4 + 2] = e2 * inv;
        aw_sh[t * 4 + 3] = e3 * inv;
    }
    // positions: tanh(offset) + ref
    if (t >= 128 && t < 192) {
        int j = t - 128;                 // j = pair*2 + coord
        int coord = j & 1;
        pos_sh[j] = tanhf(logit_sh[32 + j]) + ref[((size_t)b * 1024 + p) * 2 + coord];
    }
    __syncthreads();

    // bilinear sampling: 32 pairs x 32 channels, 8 threads per pair (float4 each)
    {
        const int lvlW_[5] = {128, 64, 32, 16, 16};
        const int lvlOff_[5] = {0, 2097152, 2621440, 2752512, 2785280};
        int W = lvlW_[l];
        int q = t >> 3;
        int cg = (t & 7) << 2;
        float fw = (float)(W - 1);
        float gx = (pos_sh[2 * q + 0] + 1.0f) * 0.5f * fw;
        float gy = (pos_sh[2 * q + 1] + 1.0f) * 0.5f * fw;
        gx = fminf(fmaxf(gx, 0.0f), fw);
        gy = fminf(fmaxf(gy, 0.0f), fw);
        float x0f = floorf(gx), y0f = floorf(gy);
        float wx = gx - x0f, wy = gy - y0f;
        int x0i = (int)x0f, y0i = (int)y0f;
        int x1i = min(x0i + 1, W - 1), y1i = min(y0i + 1, W - 1);
        const float* base = g_pfeat + lvlOff_[l] + (size_t)b * W * W * 32 + cg;
        float4 f00 = *(const float4*)(base + (size_t)(y0i * W + x0i) * 32);
        float4 f01 = *(const float4*)(base + (size_t)(y0i * W + x1i) * 32);
        float4 f10 = *(const float4*)(base + (size_t)(y1i * W + x0i) * 32);
        float4 f11 = *(const float4*)(base + (size_t)(y1i * W + x1i) * 32);
        float w00 = (1.0f - wx) * (1.0f - wy);
        float w01 = wx * (1.0f - wy);
        float w10 = (1.0f - wx) * wy;
        float w11 = wx * wy;
        float a = aw_sh[q];
        float4 r;
        r.x = a * (w00 * f00.x + w01 * f01.x + w10 * f10.x + w11 * f11.x);
        r.y = a * (w00 * f00.y + w01 * f01.y + w10 * f10.y + w11 * f11.y);
        r.z = a * (w00 * f00.z + w01 * f01.z + w10 * f10.z + w11 * f11.z);
        r.w = a * (w00 * f00.w + w01 * f01.w + w10 * f10.w + w11 * f11.w);
        *(float4*)&samp_sh[q * 32 + cg] = r;
    }
    __syncthreads();

    // combine 4 samples per head, residual, write out
    int head = t >> 5;
    int c = t & 31;
    float o = samp_sh[(head * 4 + 0) * 32 + c] + samp_sh[(head * 4 + 1) * 32 + c] +
              samp_sh[(head * 4 + 2) * 32 + c] + samp_sh[(head * 4 + 3) * 32 + c];
    float xq2 = xqv + o;
    out[xq_off + t] = xq2;

    // LN2 -> h2 scratch for MLP GEMMs
    float mean2 = block_sum_256(xq2, red) * (1.0f / 256.0f);
    float d2 = xq2 - mean2;
    float var2 = block_sum_256(d2 * d2, red) * (1.0f / 256.0f);
    float h2 = d2 * rsqrtf(var2 + 1e-5f) * n2g[t] + n2b[t];
    g_h2[(size_t)m * 256 + t] = h2;
}

// ---------------- GEMM1: g_mlp = gelu(g_h2 @ fc1_W + fc1_b)   M=20480 K=256 N=512 ----------------
__global__ void gemm_fc1(const float* __restrict__ B, const float* __restrict__ bias) {
    const int K = 256, N = 512;
    const float* A = g_h2;
    __shared__ __align__(16) float As[8][128];
    __shared__ __align__(16) float Bs[8][128];
    int tid = threadIdx.x;
    int tx = tid & 15, ty = tid >> 4;
    int m0 = blockIdx.y * 128, n0 = blockIdx.x * 128;
    int aRow = tid >> 1, aCol = (tid & 1) * 4;
    int bRow = tid >> 5, bCol = (tid & 31) * 4;
    const float* Ap = A + (size_t)(m0 + aRow) * K + aCol;
    const float* Bp = B + (size_t)bRow * N + n0 + bCol;

    float acc[8][8];
#pragma unroll
    for (int i = 0; i < 8; i++)
#pragma unroll
        for (int j = 0; j < 8; j++) acc[i][j] = 0.0f;

    for (int k0 = 0; k0 < K; k0 += 8) {
        float4 a4 = *(const float4*)Ap; Ap += 8;
        float4 b4 = *(const float4*)Bp; Bp += 8 * N;
        __syncthreads();
        As[aCol + 0][aRow] = a4.x;
        As[aCol + 1][aRow] = a4.y;
        As[aCol + 2][aRow] = a4.z;
        As[aCol + 3][aRow] = a4.w;
        *(float4*)&Bs[bRow][bCol] = b4;
        __syncthreads();
#pragma unroll
        for (int k = 0; k < 8; k++) {
            float ar[8], br[8];
            *(float4*)&ar[0] = *(const float4*)&As[k][ty * 8];
            *(float4*)&ar[4] = *(const float4*)&As[k][ty * 8 + 4];
            *(float4*)&br[0] = *(const float4*)&Bs[k][tx * 8];
            *(float4*)&br[4] = *(const float4*)&Bs[k][tx * 8 + 4];
#pragma unroll
            for (int i = 0; i < 8; i++)
#pragma unroll
                for (int j = 0; j < 8; j++) acc[i][j] = fmaf(ar[i], br[j], acc[i][j]);
        }
    }
#pragma unroll
    for (int i = 0; i < 8; i++) {
        int row = m0 + ty * 8 + i;
        float* orow = g_mlp + (size_t)row * N + n0 + tx * 8;
#pragma unroll
        for (int j = 0; j < 8; j++) {
            float v = acc[i][j] + bias[n0 + tx * 8 + j];
            orow[j] = v * normcdff(v);   // exact gelu
        }
    }
}

// ---------------- GEMM2: out[tok] += g_mlp @ fc2_W + fc2_b   M=20480 K=512 N=256 ----------------
__global__ void gemm_fc2(const float* __restrict__ B, const float* __restrict__ bias,
                         float* __restrict__ out) {
    const int K = 512, N = 256;
    const float* A = g_mlp;
    __shared__ __align__(16) float As[8][128];
    __shared__ __align__(16) float Bs[8][128];
    int tid = threadIdx.x;
    int tx = tid & 15, ty = tid >> 4;
    int m0 = blockIdx.y * 128, n0 = blockIdx.x * 128;
    int aRow = tid >> 1, aCol = (tid & 1) * 4;
    int bRow = tid >> 5, bCol = (tid & 31) * 4;
    const float* Ap = A + (size_t)(m0 + aRow) * K + aCol;
    const float* Bp = B + (size_t)bRow * N + n0 + bCol;

    float acc[8][8];
#pragma unroll
    for (int i = 0; i < 8; i++)
#pragma unroll
        for (int j = 0; j < 8; j++) acc[i][j] = 0.0f;

    for (int k0 = 0; k0 < K; k0 += 8) {
        float4 a4 = *(const float4*)Ap; Ap += 8;
        float4 b4 = *(const float4*)Bp; Bp += 8 * N;
        __syncthreads();
        As[aCol + 0][aRow] = a4.x;
        As[aCol + 1][aRow] = a4.y;
        As[aCol + 2][aRow] = a4.z;
        As[aCol + 3][aRow] = a4.w;
        *(float4*)&Bs[bRow][bCol] = b4;
        __syncthreads();
#pragma unroll
        for (int k = 0; k < 8; k++) {
            float ar[8], br[8];
            *(float4*)&ar[0] = *(const float4*)&As[k][ty * 8];
            *(float4*)&ar[4] = *(const float4*)&As[k][ty * 8 + 4];
            *(float4*)&br[0] = *(const float4*)&Bs[k][tx * 8];
            *(float4*)&br[4] = *(const float4*)&Bs[k][tx * 8 + 4];
#pragma unroll
            for (int i = 0; i < 8; i++)
#pragma unroll
                for (int j = 0; j < 8; j++) acc[i][j] = fmaf(ar[i], br[j], acc[i][j]);
        }
    }
#pragma unroll
    for (int i = 0; i < 8; i++) {
        int row = m0 + ty * 8 + i;                  // token id
        int b = row / 5120;
        int lp = row - b * 5120;
        int l = lp >> 10;
        int p = lp & 1023;
        float* orow = out + ((size_t)(b * 6 + l + 1) * 1024 + p) * 256 + n0 + tx * 8;
#pragma unroll
        for (int j = 0; j < 8; j++) {
            orow[j] = orow[j] + acc[i][j] + bias[n0 + tx * 8 + j];
        }
    }
}

// ---------------- launch ----------------
extern "C" void kernel_launch(void* const* d_in, const int* in_sizes, int n_in,
                              void* d_out, int out_size) {
    const float* x    = (const float*)d_in[0];
    const float* ref  = (const float*)d_in[1];
    const float* feat[5] = {(const float*)d_in[2], (const float*)d_in[3], (const float*)d_in[4],
                            (const float*)d_in[5], (const float*)d_in[6]};
    const float* n1g = (const float*)d_in[7];
    const float* n1b = (const float*)d_in[8];
    const float* awW = (const float*)d_in[9];
    const float* awb = (const float*)d_in[10];
    const float* soW = (const float*)d_in[11];
    const float* sob = (const float*)d_in[12];
    const float* epW[5] = {(const float*)d_in[13], (const float*)d_in[15], (const float*)d_in[17],
                           (const float*)d_in[19], (const float*)d_in[21]};
    const float* epb[5] = {(const float*)d_in[14], (const float*)d_in[16], (const float*)d_in[18],
                           (const float*)d_in[20], (const float*)d_in[22]};
    const float* n2g  = (const float*)d_in[23];
    const float* n2b  = (const float*)d_in[24];
    const float* fc1W = (const float*)d_in[25];
    const float* fc1b = (const float*)d_in[26];
    const float* fc2W = (const float*)d_in[27];
    const float* fc2b = (const float*)d_in[28];
    float* out = (float*)d_out;

    const int Cs[5]  = {64, 128, 256, 512, 256};
    const int HWs[5] = {16384, 4096, 1024, 256, 256};
    const int offs[5] = {0, 2097152, 2621440, 2752512, 2785280};

    for (int lvl = 0; lvl < 5; lvl++) {
        int npix = 4 * HWs[lvl];
        proj_kernel<<<npix / 128, 128>>>(feat[lvl], epW[lvl], epb[lvl], Cs[lvl], HWs[lvl], offs[lvl]);
    }
    copy_x0_kernel<<<1024, 256>>>(x, out);
    token_kernel<<<20480, 256>>>(x, ref, n1g, n1b, awW, awb, soW, sob, n2g, n2b, out);
    gemm_fc1<<<dim3(4, 160), 256>>>(fc1W, fc1b);
    gemm_fc2<<<dim3(2, 160), 256>>>(fc2W, fc2b, out);
}

// round 3
// speedup vs baseline: 1.9692x; 1.9692x over previous
#include <cuda_runtime.h>
#include <math.h>

// ---------------- scratch (static device globals; no allocation) ----------------
// pfeat: per-level projected features, layout [level][b][y][x][32ch]
static __device__ __align__(16) float g_pfeat[2818048];
static __device__ __align__(16) float g_h2[20480 * 256];
static __device__ __align__(16) float g_mlp[20480 * 512];

// ---------------- tf32 helper ----------------
__device__ __forceinline__ unsigned f2tf(float x) {
    unsigned u;
    asm("cvt.rna.tf32.f32 %0, %1;" : "=r"(u) : "f"(x));
    return u;
}

// ---------------- feature projection: warp per pixel ----------------
// out[pix][j] = sum_c feat[b,c,pix] * W[c,j] + b[j], j = lane (32 outputs)
__global__ __launch_bounds__(256) void proj_warp(const float* __restrict__ feat,
                                                 const float* __restrict__ Wp,
                                                 const float* __restrict__ bp,
                                                 int C, int HW, int outOff) {
    __shared__ float Wsh[256 * 32];
    int lane = threadIdx.x & 31, wid = threadIdx.x >> 5;
    int pix = blockIdx.x * 8 + wid;
    int b = pix / HW;
    int idx = pix - b * HW;
    const float* fbase = feat + (size_t)b * C * HW + idx;

    float acc = bp[lane];
    for (int cb = 0; cb < C; cb += 256) {
        int cl = min(256, C - cb);
        __syncthreads();
        for (int i = threadIdx.x; i < cl * 32; i += 256)
            Wsh[i] = Wp[cb * 32 + i];
        __syncthreads();
        for (int c0 = 0; c0 < cl; c0 += 32) {
            float fv = __ldg(fbase + (size_t)(cb + c0 + lane) * HW);
#pragma unroll
            for (int cc = 0; cc < 32; cc++)
                acc = fmaf(__shfl_sync(0xffffffffu, fv, cc), Wsh[(c0 + cc) * 32 + lane], acc);
        }
    }
    g_pfeat[outOff + (size_t)pix * 32 + lane] = acc;
}

// ---------------- copy x0 token slice to output ----------------
__global__ void copy_x0_kernel(const float* __restrict__ x, float* __restrict__ out) {
    int i = blockIdx.x * blockDim.x + threadIdx.x;   // 262144 float4s total
    int b = i >> 16;
    int r = i & 65535;
    const float4* xi = (const float4*)x;
    float4* oo = (float4*)out;
    size_t off = (size_t)b * (6 * 65536) + r;
    oo[off] = xi[off];
}

// ---------------- fused token kernel: 8 tokens per block, 256 threads ----------------
__global__ __launch_bounds__(256) void token_fused(
    const float* __restrict__ x, const float* __restrict__ ref,
    const float* __restrict__ n1g, const float* __restrict__ n1b,
    const float* __restrict__ awW, const float* __restrict__ awb,
    const float* __restrict__ soW, const float* __restrict__ sob,
    const float* __restrict__ n2g, const float* __restrict__ n2b,
    float* __restrict__ out) {
    __shared__ float h_sh[8][256];        // 8KB
    __shared__ float logit_sh[8][96];     // 3KB
    __shared__ float aw_sh[8][32];        // 1KB
    __shared__ float pos_sh[8][64];       // 2KB
    __shared__ float samp_sh[8][32 * 33]; // 33KB (33-pad: conflict-free)

    int t = threadIdx.x, lane = t & 31, w = t >> 5;
    int m0 = blockIdx.x * 8;
    int b = m0 / 5120;
    int lp = m0 - b * 5120;
    int l = lp >> 10;
    int p0 = lp & 1023;
    size_t base_q = ((size_t)(b * 6 + l + 1) * 1024 + p0) * 256;
    size_t base_0 = ((size_t)(b * 6) * 1024 + p0) * 256;

    // ---- P1: LN1, warp w handles token w ----
    {
        size_t xq_off = base_q + (size_t)w * 256;
        size_t x0_off = base_0 + (size_t)w * 256;
        float sv[8];
        float s = 0.0f;
#pragma unroll
        for (int i = 0; i < 8; i++) {
            int c = lane + 32 * i;
            sv[i] = x[xq_off + c] + x[x0_off + c];
            s += sv[i];
        }
#pragma unroll
        for (int o = 16; o > 0; o >>= 1) s += __shfl_xor_sync(0xffffffffu, s, o);
        float mean = s * (1.0f / 256.0f);
        float v = 0.0f;
#pragma unroll
        for (int i = 0; i < 8; i++) { float d = sv[i] - mean; v += d * d; }
#pragma unroll
        for (int o = 16; o > 0; o >>= 1) v += __shfl_xor_sync(0xffffffffu, v, o);
        float rstd = rsqrtf(v * (1.0f / 256.0f) + 1e-5f);
#pragma unroll
        for (int i = 0; i < 8; i++) {
            int c = lane + 32 * i;
            h_sh[w][c] = (sv[i] - mean) * rstd * n1g[c] + n1b[c];
        }
    }
    __syncthreads();

    // ---- P2: head logits, 8 tok x 96 cols; thread handles 4 adjacent cols ----
    if (t < 192) {
        int tok = t / 24;
        int jj = (t - tok * 24) * 4;           // 0,4,...,92 (never straddles the 32 boundary)
        const float* wcol;
        int stride;
        float a0, a1, a2, a3;
        if (jj < 32) {
            wcol = awW + jj; stride = 32;
            a0 = awb[jj]; a1 = awb[jj + 1]; a2 = awb[jj + 2]; a3 = awb[jj + 3];
        } else {
            wcol = soW + (jj - 32); stride = 64;
            a0 = sob[jj - 32]; a1 = sob[jj - 31]; a2 = sob[jj - 30]; a3 = sob[jj - 29];
        }
        const float* hrow = h_sh[tok];
#pragma unroll 8
        for (int k = 0; k < 256; k++) {
            float hv = hrow[k];
            float4 w4 = *(const float4*)(wcol + (size_t)k * stride);
            a0 = fmaf(hv, w4.x, a0);
            a1 = fmaf(hv, w4.y, a1);
            a2 = fmaf(hv, w4.z, a2);
            a3 = fmaf(hv, w4.w, a3);
        }
        logit_sh[tok][jj + 0] = a0;
        logit_sh[tok][jj + 1] = a1;
        logit_sh[tok][jj + 2] = a2;
        logit_sh[tok][jj + 3] = a3;
    }
    __syncthreads();

    // ---- P3: softmax (64 threads) + tanh positions (512 entries) ----
    if (t < 64) {
        int tok = t >> 3, hd = t & 7;
        float v0 = logit_sh[tok][hd * 4 + 0], v1 = logit_sh[tok][hd * 4 + 1];
        float v2 = logit_sh[tok][hd * 4 + 2], v3 = logit_sh[tok][hd * 4 + 3];
        float mx = fmaxf(fmaxf(v0, v1), fmaxf(v2, v3));
        float e0 = expf(v0 - mx), e1 = expf(v1 - mx), e2 = expf(v2 - mx), e3 = expf(v3 - mx);
        float inv = 1.0f / (e0 + e1 + e2 + e3);
        aw_sh[tok][hd * 4 + 0] = e0 * inv;
        aw_sh[tok][hd * 4 + 1] = e1 * inv;
        aw_sh[tok][hd * 4 + 2] = e2 * inv;
        aw_sh[tok][hd * 4 + 3] = e3 * inv;
    }
#pragma unroll
    for (int i = 0; i < 2; i++) {
        int o = t + 256 * i;                 // 0..511
        int tok = o >> 6, j = o & 63;
        pos_sh[tok][j] = tanhf(logit_sh[tok][32 + j]) +
                         ref[((size_t)b * 1024 + p0 + tok) * 2 + (j & 1)];
    }
    __syncthreads();

    // ---- P4: bilinear sampling; thread = (token, sample-pair) ----
    {
        const int lvlW_[5] = {128, 64, 32, 16, 16};
        const int lvlOff_[5] = {0, 2097152, 2621440, 2752512, 2785280};
        int tok = t >> 5, q = lane;
        int W = lvlW_[l];
        float fw = (float)(W - 1);
        float gx = fminf(fmaxf((pos_sh[tok][2 * q + 0] + 1.0f) * 0.5f * fw, 0.0f), fw);
        float gy = fminf(fmaxf((pos_sh[tok][2 * q + 1] + 1.0f) * 0.5f * fw, 0.0f), fw);
        float x0f = floorf(gx), y0f = floorf(gy);
        float wx = gx - x0f, wy = gy - y0f;
        int x0i = (int)x0f, y0i = (int)y0f;
        int x1i = min(x0i + 1, W - 1), y1i = min(y0i + 1, W - 1);
        const float* bb = g_pfeat + lvlOff_[l] + (size_t)b * W * W * 32;
        const float* p00 = bb + (size_t)(y0i * W + x0i) * 32;
        const float* p01 = bb + (size_t)(y0i * W + x1i) * 32;
        const float* p10 = bb + (size_t)(y1i * W + x0i) * 32;
        const float* p11 = bb + (size_t)(y1i * W + x1i) * 32;
        float a = aw_sh[tok][q];
        float aw00 = a * (1.0f - wx) * (1.0f - wy);
        float aw01 = a * wx * (1.0f - wy);
        float aw10 = a * (1.0f - wx) * wy;
        float aw11 = a * wx * wy;
        float* dst = &samp_sh[tok][q * 33];
#pragma unroll
        for (int c4 = 0; c4 < 32; c4 += 4) {
            float4 f00 = *(const float4*)(p00 + c4);
            float4 f01 = *(const float4*)(p01 + c4);
            float4 f10 = *(const float4*)(p10 + c4);
            float4 f11 = *(const float4*)(p11 + c4);
            dst[c4 + 0] = aw00 * f00.x + aw01 * f01.x + aw10 * f10.x + aw11 * f11.x;
            dst[c4 + 1] = aw00 * f00.y + aw01 * f01.y + aw10 * f10.y + aw11 * f11.y;
            dst[c4 + 2] = aw00 * f00.z + aw01 * f01.z + aw10 * f10.z + aw11 * f11.z;
            dst[c4 + 3] = aw00 * f00.w + aw01 * f01.w + aw10 * f10.w + aw11 * f11.w;
        }
    }
    __syncthreads();

    // ---- P5: head combine + residual + LN2 (warp w = token w) ----
    {
        size_t xq_off = base_q + (size_t)w * 256;
        float o8[8];
        float s = 0.0f;
#pragma unroll
        for (int i = 0; i < 8; i++) {
            int c = lane + 32 * i;            // head = i, ch-within-head = lane
            int hq = i * 4;
            float ov = samp_sh[w][(hq + 0) * 33 + lane] + samp_sh[w][(hq + 1) * 33 + lane] +
                       samp_sh[w][(hq + 2) * 33 + lane] + samp_sh[w][(hq + 3) * 33 + lane];
            float xq2 = x[xq_off + c] + ov;
            out[xq_off + c] = xq2;
            o8[i] = xq2;
            s += xq2;
        }
#pragma unroll
        for (int o = 16; o > 0; o >>= 1) s += __shfl_xor_sync(0xffffffffu, s, o);
        float mean = s * (1.0f / 256.0f);
        float v = 0.0f;
#pragma unroll
        for (int i = 0; i < 8; i++) { float d = o8[i] - mean; v += d * d; }
#pragma unroll
        for (int o = 16; o > 0; o >>= 1) v += __shfl_xor_sync(0xffffffffu, v, o);
        float rstd = rsqrtf(v * (1.0f / 256.0f) + 1e-5f);
#pragma unroll
        for (int i = 0; i < 8; i++) {
            int c = lane + 32 * i;
            g_h2[(size_t)(m0 + w) * 256 + c] = (o8[i] - mean) * rstd * n2g[c] + n2b[c];
        }
    }
}

// ---------------- tf32 tensor-core GEMM ----------------
// C[M=20480, NDIM] = A[M,K] @ B[K,NDIM] + bias, with epilogue:
//   EPI=0: A=g_h2  (K=256, N=512) -> g_mlp = gelu(.)
//   EPI=1: A=g_mlp (K=512, N=256) -> out[token scatter] += .
template <int K, int NDIM, int EPI>
__global__ __launch_bounds__(256, 2) void mma_gemm(const float* __restrict__ B,
                                                   const float* __restrict__ bias,
                                                   float* __restrict__ out) {
    const float* A = (EPI == 0) ? (const float*)g_h2 : (const float*)g_mlp;
    __shared__ unsigned As[2][128][20];   // [row][k], pad 20 -> conflict-free frags
    __shared__ unsigned Bs[2][16][132];   // [k][col], pad 132 -> conflict-free frags

    int tid = threadIdx.x;
    int m0 = blockIdx.y * 128, n0 = blockIdx.x * 128;

    // global load mapping
    int aRow = tid >> 1, aCol = (tid & 1) * 8;
    int bR = tid >> 5;                       // 0..7 (and +8)
    int bC = (tid & 31) * 4;
    const float* Ap = A + (size_t)(m0 + aRow) * K + aCol;
    const float* Bp0 = B + (size_t)bR * NDIM + n0 + bC;
    const float* Bp1 = B + (size_t)(bR + 8) * NDIM + n0 + bC;

    // fragment mapping
    int lane = tid & 31, wid = tid >> 5;
    int wm = wid & 3, wn = wid >> 2;         // 4x2 warps -> 32x64 warp tile
    int gid = lane >> 2, tig = lane & 3;

    float acc[2][8][4];
#pragma unroll
    for (int mt = 0; mt < 2; mt++)
#pragma unroll
        for (int nt = 0; nt < 8; nt++)
#pragma unroll
            for (int r = 0; r < 4; r++) acc[mt][nt][r] = 0.0f;

    float4 a0, a1, b0, b1;
    const int NK = K / 16;

    // prologue: tile 0
    {
        a0 = *(const float4*)Ap;
        a1 = *(const float4*)(Ap + 4);
        b0 = *(const float4*)Bp0;
        b1 = *(const float4*)Bp1;
        uint4 u;
        u.x = f2tf(a0.x); u.y = f2tf(a0.y); u.z = f2tf(a0.z); u.w = f2tf(a0.w);
        *(uint4*)&As[0][aRow][aCol] = u;
        u.x = f2tf(a1.x); u.y = f2tf(a1.y); u.z = f2tf(a1.z); u.w = f2tf(a1.w);
        *(uint4*)&As[0][aRow][aCol + 4] = u;
        u.x = f2tf(b0.x); u.y = f2tf(b0.y); u.z = f2tf(b0.z); u.w = f2tf(b0.w);
        *(uint4*)&Bs[0][bR][bC] = u;
        u.x = f2tf(b1.x); u.y = f2tf(b1.y); u.z = f2tf(b1.z); u.w = f2tf(b1.w);
        *(uint4*)&Bs[0][bR + 8][bC] = u;
    }
    __syncthreads();

    for (int ks = 0; ks < NK; ks++) {
        int buf = ks & 1;
        if (ks + 1 < NK) {
            const float* ap = Ap + (ks + 1) * 16;
            a0 = *(const float4*)ap;
            a1 = *(const float4*)(ap + 4);
            const float* bp0 = Bp0 + (size_t)(ks + 1) * 16 * NDIM;
            const float* bp1 = Bp1 + (size_t)(ks + 1) * 16 * NDIM;
            b0 = *(const float4*)bp0;
            b1 = *(const float4*)bp1;
        }
        // compute on buf
#pragma unroll
        for (int kk = 0; kk < 2; kk++) {
            unsigned af[2][4];
#pragma unroll
            for (int mt = 0; mt < 2; mt++) {
                int r = wm * 32 + mt * 16 + gid;
                int c = kk * 8 + tig;
                af[mt][0] = As[buf][r][c];
                af[mt][1] = As[buf][r + 8][c];
                af[mt][2] = As[buf][r][c + 4];
                af[mt][3] = As[buf][r + 8][c + 4];
            }
#pragma unroll
            for (int nt = 0; nt < 8; nt++) {
                int cb = wn * 64 + nt * 8 + gid;
                unsigned bf0 = Bs[buf][kk * 8 + tig][cb];
                unsigned bf1 = Bs[buf][kk * 8 + tig + 4][cb];
#pragma unroll
                for (int mt = 0; mt < 2; mt++) {
                    asm volatile(
                        "mma.sync.aligned.m16n8k8.row.col.f32.tf32.tf32.f32 "
                        "{%0,%1,%2,%3},{%4,%5,%6,%7},{%8,%9},{%0,%1,%2,%3};"
                        : "+f"(acc[mt][nt][0]), "+f"(acc[mt][nt][1]),
                          "+f"(acc[mt][nt][2]), "+f"(acc[mt][nt][3])
                        : "r"(af[mt][0]), "r"(af[mt][1]), "r"(af[mt][2]), "r"(af[mt][3]),
                          "r"(bf0), "r"(bf1));
                }
            }
        }
        if (ks + 1 < NK) {
            int nb = (ks + 1) & 1;
            uint4 u;
            u.x = f2tf(a0.x); u.y = f2tf(a0.y); u.z = f2tf(a0.z); u.w = f2tf(a0.w);
            *(uint4*)&As[nb][aRow][aCol] = u;
            u.x = f2tf(a1.x); u.y = f2tf(a1.y); u.z = f2tf(a1.z); u.w = f2tf(a1.w);
            *(uint4*)&As[nb][aRow][aCol + 4] = u;
            u.x = f2tf(b0.x); u.y = f2tf(b0.y); u.z = f2tf(b0.z); u.w = f2tf(b0.w);
            *(uint4*)&Bs[nb][bR][bC] = u;
            u.x = f2tf(b1.x); u.y = f2tf(b1.y); u.z = f2tf(b1.z); u.w = f2tf(b1.w);
            *(uint4*)&Bs[nb][bR + 8][bC] = u;
        }
        __syncthreads();
    }

    // epilogue
#pragma unroll
    for (int mt = 0; mt < 2; mt++) {
#pragma unroll
        for (int nt = 0; nt < 8; nt++) {
            int r0 = m0 + wm * 32 + mt * 16 + gid;
            int c = n0 + wn * 64 + nt * 8 + 2 * tig;
            float bv0 = __ldg(bias + c), bv1 = __ldg(bias + c + 1);
            if (EPI == 0) {
                float v0 = acc[mt][nt][0] + bv0, v1 = acc[mt][nt][1] + bv1;
                float v2 = acc[mt][nt][2] + bv0, v3 = acc[mt][nt][3] + bv1;
                float2 w0 = make_float2(v0 * normcdff(v0), v1 * normcdff(v1));
                float2 w1 = make_float2(v2 * normcdff(v2), v3 * normcdff(v3));
                *(float2*)&g_mlp[(size_t)r0 * 512 + c] = w0;
                *(float2*)&g_mlp[(size_t)(r0 + 8) * 512 + c] = w1;
            } else {
#pragma unroll
                for (int half = 0; half < 2; half++) {
                    int row = r0 + half * 8;
                    int bb = row / 5120;
                    int lpp = row - bb * 5120;
                    int ll = lpp >> 10;
                    int pp = lpp & 1023;
                    float* orow = out + ((size_t)(bb * 6 + ll + 1) * 1024 + pp) * 256 + c;
                    float2 cur = *(float2*)orow;
                    cur.x += acc[mt][nt][half * 2 + 0] + bv0;
                    cur.y += acc[mt][nt][half * 2 + 1] + bv1;
                    *(float2*)orow = cur;
                }
            }
        }
    }
}

// ---------------- launch ----------------
extern "C" void kernel_launch(void* const* d_in, const int* in_sizes, int n_in,
                              void* d_out, int out_size) {
    const float* x    = (const float*)d_in[0];
    const float* ref  = (const float*)d_in[1];
    const float* feat[5] = {(const float*)d_in[2], (const float*)d_in[3], (const float*)d_in[4],
                            (const float*)d_in[5], (const float*)d_in[6]};
    const float* n1g = (const float*)d_in[7];
    const float* n1b = (const float*)d_in[8];
    const float* awW = (const float*)d_in[9];
    const float* awb = (const float*)d_in[10];
    const float* soW = (const float*)d_in[11];
    const float* sob = (const float*)d_in[12];
    const float* epW[5] = {(const float*)d_in[13], (const float*)d_in[15], (const float*)d_in[17],
                           (const float*)d_in[19], (const float*)d_in[21]};
    const float* epb[5] = {(const float*)d_in[14], (const float*)d_in[16], (const float*)d_in[18],
                           (const float*)d_in[20], (const float*)d_in[22]};
    const float* n2g  = (const float*)d_in[23];
    const float* n2b  = (const float*)d_in[24];
    const float* fc1W = (const float*)d_in[25];
    const float* fc1b = (const float*)d_in[26];
    const float* fc2W = (const float*)d_in[27];
    const float* fc2b = (const float*)d_in[28];
    float* out = (float*)d_out;

    const int Cs[5]   = {64, 128, 256, 512, 256};
    const int HWs[5]  = {16384, 4096, 1024, 256, 256};
    const int offs[5] = {0, 2097152, 2621440, 2752512, 2785280};

    for (int lvl = 0; lvl < 5; lvl++) {
        int npix = 4 * HWs[lvl];
        proj_warp<<<npix / 8, 256>>>(feat[lvl], epW[lvl], epb[lvl], Cs[lvl], HWs[lvl], offs[lvl]);
    }
    copy_x0_kernel<<<1024, 256>>>(x, out);
    token_fused<<<2560, 256>>>(x, ref, n1g, n1b, awW, awb, soW, sob, n2g, n2b, out);
    mma_gemm<256, 512, 0><<<dim3(4, 160), 256>>>(fc1W, fc1b, out);
    mma_gemm<512, 256, 1><<<dim3(2, 160), 256>>>(fc2W, fc2b, out);
}

// round 4
// speedup vs baseline: 2.2611x; 1.1482x over previous
#include <cuda_runtime.h>
#include <cuda_bf16.h>
#include <math.h>

// ---------------- scratch (static device globals; no allocation) ----------------
static __device__ __align__(16) float g_pfeat[2818048];
static __device__ __align__(16) float g_h2[20480 * 256];
static __device__ __align__(16) float g_mlp[20480 * 512];

// ---------------- merged feature projection: one launch, all 5 levels ----------------
// out[pix][j] = sum_c feat[b,c,pix] * W[c,j] + b[j]
// block = 64 pixels of one level, full C. 256 threads = 4 groups x 64 pixels,
// group g computes output channels [8g, 8g+8).
struct ProjParams {
    const float* feat[5];
    const float* W[5];
    const float* bias[5];
};

__global__ __launch_bounds__(256) void proj_all(ProjParams P) {
    const int starts[6] = {0, 1024, 1280, 1344, 1360, 1376};
    const int Cs[5]   = {64, 128, 256, 512, 256};
    const int HWs[5]  = {16384, 4096, 1024, 256, 256};
    const int offs[5] = {0, 2097152, 2621440, 2752512, 2785280};

    __shared__ float featS[32][64];
    __shared__ float WS[32][32];

    int blk = blockIdx.x;
    int l = 0;
#pragma unroll
    for (int i = 0; i < 4; i++) if (blk >= starts[l + 1]) l++;
    int tile = blk - starts[l];
    int C = Cs[l], HW = HWs[l];
    int pixbase = tile * 64;              // pixel index within [0, 4*HW)
    int b = pixbase / HW;
    int idx0 = pixbase - b * HW;

    const float* feat = P.feat[l];
    const float* Wp = P.W[l];
    const float* bp = P.bias[l];

    int t = threadIdx.x;
    int px = t & 63, grp = t >> 6;

    float acc[8];
#pragma unroll
    for (int j = 0; j < 8; j++) acc[j] = bp[grp * 8 + j];

    size_t fbase = ((size_t)b * C) * HW + idx0;

    for (int c0 = 0; c0 < C; c0 += 32) {
        __syncthreads();
        // stage 32 channels x 64 pixels, coalesced along pixel dim
#pragma unroll
        for (int k = 0; k < 8; k++) {
            int j = t + k * 256;          // 0..2047
            int cc = j >> 6, pp = j & 63;
            featS[cc][pp] = feat[fbase + (size_t)(c0 + cc) * HW + pp];
        }
        // stage W chunk 32x32
#pragma unroll
        for (int k = 0; k < 4; k++) {
            int j = t + k * 256;          // 0..1023
            WS[j >> 5][j & 31] = Wp[(size_t)(c0 + (j >> 5)) * 32 + (j & 31)];
        }
        __syncthreads();
#pragma unroll
        for (int cc = 0; cc < 32; cc++) {
            float fv = featS[cc][px];
#pragma unroll
            for (int j = 0; j < 8; j++)
                acc[j] = fmaf(fv, WS[cc][grp * 8 + j], acc[j]);
        }
    }
    float* o = g_pfeat + offs[l] + (size_t)(pixbase + px) * 32 + grp * 8;
    *(float4*)o = make_float4(acc[0], acc[1], acc[2], acc[3]);
    *(float4*)(o + 4) = make_float4(acc[4], acc[5], acc[6], acc[7]);
}

// ---------------- copy x0 token slice to output ----------------
__global__ void copy_x0_kernel(const float* __restrict__ x, float* __restrict__ out) {
    int i = blockIdx.x * blockDim.x + threadIdx.x;   // 262144 float4s total
    int b = i >> 16;
    int r = i & 65535;
    const float4* xi = (const float4*)x;
    float4* oo = (float4*)out;
    size_t off = (size_t)b * (6 * 65536) + r;
    oo[off] = xi[off];
}

// ---------------- fused token kernel: 8 tokens per block, 256 threads ----------------
__global__ __launch_bounds__(256) void token_fused(
    const float* __restrict__ x, const float* __restrict__ ref,
    const float* __restrict__ n1g, const float* __restrict__ n1b,
    const float* __restrict__ awW, const float* __restrict__ awb,
    const float* __restrict__ soW, const float* __restrict__ sob,
    const float* __restrict__ n2g, const float* __restrict__ n2b,
    float* __restrict__ out) {
    __shared__ float h_sh[8][256];
    __shared__ float logit_sh[8][96];
    __shared__ float aw_sh[8][32];
    __shared__ float pos_sh[8][64];
    __shared__ float samp_sh[8][32 * 33];

    int t = threadIdx.x, lane = t & 31, w = t >> 5;
    int m0 = blockIdx.x * 8;
    int b = m0 / 5120;
    int lp = m0 - b * 5120;
    int l = lp >> 10;
    int p0 = lp & 1023;
    size_t base_q = ((size_t)(b * 6 + l + 1) * 1024 + p0) * 256;
    size_t base_0 = ((size_t)(b * 6) * 1024 + p0) * 256;

    // ---- P1: LN1, warp w handles token w ----
    {
        size_t xq_off = base_q + (size_t)w * 256;
        size_t x0_off = base_0 + (size_t)w * 256;
        float sv[8];
        float s = 0.0f;
#pragma unroll
        for (int i = 0; i < 8; i++) {
            int c = lane + 32 * i;
            sv[i] = x[xq_off + c] + x[x0_off + c];
            s += sv[i];
        }
#pragma unroll
        for (int o = 16; o > 0; o >>= 1) s += __shfl_xor_sync(0xffffffffu, s, o);
        float mean = s * (1.0f / 256.0f);
        float v = 0.0f;
#pragma unroll
        for (int i = 0; i < 8; i++) { float d = sv[i] - mean; v += d * d; }
#pragma unroll
        for (int o = 16; o > 0; o >>= 1) v += __shfl_xor_sync(0xffffffffu, v, o);
        float rstd = rsqrtf(v * (1.0f / 256.0f) + 1e-5f);
#pragma unroll
        for (int i = 0; i < 8; i++) {
            int c = lane + 32 * i;
            h_sh[w][c] = (sv[i] - mean) * rstd * n1g[c] + n1b[c];
        }
    }
    __syncthreads();

    // ---- P2: head logits, 8 tok x 96 cols; thread handles 4 adjacent cols ----
    if (t < 192) {
        int tok = t / 24;
        int jj = (t - tok * 24) * 4;
        const float* wcol;
        int stride;
        float a0, a1, a2, a3;
        if (jj < 32) {
            wcol = awW + jj; stride = 32;
            a0 = awb[jj]; a1 = awb[jj + 1]; a2 = awb[jj + 2]; a3 = awb[jj + 3];
        } else {
            wcol = soW + (jj - 32); stride = 64;
            a0 = sob[jj - 32]; a1 = sob[jj - 31]; a2 = sob[jj - 30]; a3 = sob[jj - 29];
        }
        const float* hrow = h_sh[tok];
#pragma unroll 8
        for (int k = 0; k < 256; k++) {
            float hv = hrow[k];
            float4 w4 = *(const float4*)(wcol + (size_t)k * stride);
            a0 = fmaf(hv, w4.x, a0);
            a1 = fmaf(hv, w4.y, a1);
            a2 = fmaf(hv, w4.z, a2);
            a3 = fmaf(hv, w4.w, a3);
        }
        logit_sh[tok][jj + 0] = a0;
        logit_sh[tok][jj + 1] = a1;
        logit_sh[tok][jj + 2] = a2;
        logit_sh[tok][jj + 3] = a3;
    }
    __syncthreads();

    // ---- P3: softmax + tanh positions ----
    if (t < 64) {
        int tok = t >> 3, hd = t & 7;
        float v0 = logit_sh[tok][hd * 4 + 0], v1 = logit_sh[tok][hd * 4 + 1];
        float v2 = logit_sh[tok][hd * 4 + 2], v3 = logit_sh[tok][hd * 4 + 3];
        float mx = fmaxf(fmaxf(v0, v1), fmaxf(v2, v3));
        float e0 = expf(v0 - mx), e1 = expf(v1 - mx), e2 = expf(v2 - mx), e3 = expf(v3 - mx);
        float inv = 1.0f / (e0 + e1 + e2 + e3);
        aw_sh[tok][hd * 4 + 0] = e0 * inv;
        aw_sh[tok][hd * 4 + 1] = e1 * inv;
        aw_sh[tok][hd * 4 + 2] = e2 * inv;
        aw_sh[tok][hd * 4 + 3] = e3 * inv;
    }
#pragma unroll
    for (int i = 0; i < 2; i++) {
        int o = t + 256 * i;
        int tok = o >> 6, j = o & 63;
        pos_sh[tok][j] = tanhf(logit_sh[tok][32 + j]) +
                         ref[((size_t)b * 1024 + p0 + tok) * 2 + (j & 1)];
    }
    __syncthreads();

    // ---- P4: bilinear sampling; thread = (token, sample-pair) ----
    {
        const int lvlW_[5] = {128, 64, 32, 16, 16};
        const int lvlOff_[5] = {0, 2097152, 2621440, 2752512, 2785280};
        int tok = t >> 5, q = lane;
        int W = lvlW_[l];
        float fw = (float)(W - 1);
        float gx = fminf(fmaxf((pos_sh[tok][2 * q + 0] + 1.0f) * 0.5f * fw, 0.0f), fw);
        float gy = fminf(fmaxf((pos_sh[tok][2 * q + 1] + 1.0f) * 0.5f * fw, 0.0f), fw);
        float x0f = floorf(gx), y0f = floorf(gy);
        float wx = gx - x0f, wy = gy - y0f;
        int x0i = (int)x0f, y0i = (int)y0f;
        int x1i = min(x0i + 1, W - 1), y1i = min(y0i + 1, W - 1);
        const float* bb = g_pfeat + lvlOff_[l] + (size_t)b * W * W * 32;
        const float* p00 = bb + (size_t)(y0i * W + x0i) * 32;
        const float* p01 = bb + (size_t)(y0i * W + x1i) * 32;
        const float* p10 = bb + (size_t)(y1i * W + x0i) * 32;
        const float* p11 = bb + (size_t)(y1i * W + x1i) * 32;
        float a = aw_sh[tok][q];
        float aw00 = a * (1.0f - wx) * (1.0f - wy);
        float aw01 = a * wx * (1.0f - wy);
        float aw10 = a * (1.0f - wx) * wy;
        float aw11 = a * wx * wy;
        float* dst = &samp_sh[tok][q * 33];
#pragma unroll
        for (int c4 = 0; c4 < 32; c4 += 4) {
            float4 f00 = *(const float4*)(p00 + c4);
            float4 f01 = *(const float4*)(p01 + c4);
            float4 f10 = *(const float4*)(p10 + c4);
            float4 f11 = *(const float4*)(p11 + c4);
            dst[c4 + 0] = aw00 * f00.x + aw01 * f01.x + aw10 * f10.x + aw11 * f11.x;
            dst[c4 + 1] = aw00 * f00.y + aw01 * f01.y + aw10 * f10.y + aw11 * f11.y;
            dst[c4 + 2] = aw00 * f00.z + aw01 * f01.z + aw10 * f10.z + aw11 * f11.z;
            dst[c4 + 3] = aw00 * f00.w + aw01 * f01.w + aw10 * f10.w + aw11 * f11.w;
        }
    }
    __syncthreads();

    // ---- P5: head combine + residual + LN2 ----
    {
        size_t xq_off = base_q + (size_t)w * 256;
        float o8[8];
        float s = 0.0f;
#pragma unroll
        for (int i = 0; i < 8; i++) {
            int c = lane + 32 * i;
            int hq = i * 4;
            float ov = samp_sh[w][(hq + 0) * 33 + lane] + samp_sh[w][(hq + 1) * 33 + lane] +
                       samp_sh[w][(hq + 2) * 33 + lane] + samp_sh[w][(hq + 3) * 33 + lane];
            float xq2 = x[xq_off + c] + ov;
            out[xq_off + c] = xq2;
            o8[i] = xq2;
            s += xq2;
        }
#pragma unroll
        for (int o = 16; o > 0; o >>= 1) s += __shfl_xor_sync(0xffffffffu, s, o);
        float mean = s * (1.0f / 256.0f);
        float v = 0.0f;
#pragma unroll
        for (int i = 0; i < 8; i++) { float d = o8[i] - mean; v += d * d; }
#pragma unroll
        for (int o = 16; o > 0; o >>= 1) v += __shfl_xor_sync(0xffffffffu, v, o);
        float rstd = rsqrtf(v * (1.0f / 256.0f) + 1e-5f);
#pragma unroll
        for (int i = 0; i < 8; i++) {
            int c = lane + 32 * i;
            g_h2[(size_t)(m0 + w) * 256 + c] = (o8[i] - mean) * rstd * n2g[c] + n2b[c];
        }
    }
}

// ---------------- bf16 tensor-core GEMM (m16n8k16, fp32 accumulate) ----------------
//   EPI=0: A=g_h2  (K=256, N=512) -> g_mlp = gelu(.)
//   EPI=1: A=g_mlp (K=512, N=256) -> out[token scatter] += .
__device__ __forceinline__ unsigned pack_bf2(float lo, float hi) {
    __nv_bfloat162 h = __floats2bfloat162_rn(lo, hi);
    return *(unsigned*)&h;
}

template <int K, int NDIM, int EPI>
__global__ __launch_bounds__(256, 2) void mma_gemm(const float* __restrict__ B,
                                                   const float* __restrict__ bias,
                                                   float* __restrict__ out) {
    const float* A = (EPI == 0) ? (const float*)g_h2 : (const float*)g_mlp;
    // packed bf16 pairs along k. Pad: As stride 12 (== 4 mod 32, 4*odd -> frag conflict-free),
    // Bs stride 136 (== 8 mod 32 -> frag conflict-free).
    __shared__ unsigned As[2][128][12];   // [row][kp]  kp packs k=2kp,2kp+1
    __shared__ unsigned Bs[2][8][136];    // [kp][col]

    int tid = threadIdx.x;
    int m0 = blockIdx.y * 128, n0 = blockIdx.x * 128;

    // global load mapping
    int aRow = tid >> 1, aColP = (tid & 1) * 4;      // packed col 0 or 4
    int bR = tid >> 5;                                // kp 0..7
    int bC = (tid & 31) * 4;
    const float* Ap = A + (size_t)(m0 + aRow) * K + aColP * 2;
    const float* Bp = B + (size_t)(2 * bR) * NDIM + n0 + bC;

    // fragment mapping
    int lane = tid & 31, wid = tid >> 5;
    int wm = wid & 3, wn = wid >> 2;                  // 4x2 warps -> 32x64 warp tile
    int gid = lane >> 2, tig = lane & 3;

    float acc[2][8][4];
#pragma unroll
    for (int mt = 0; mt < 2; mt++)
#pragma unroll
        for (int nt = 0; nt < 8; nt++)
#pragma unroll
            for (int r = 0; r < 4; r++) acc[mt][nt][r] = 0.0f;

    float4 a0, a1, b0, b1;
    const int NK = K / 16;

    // prologue: tile 0
    {
        a0 = *(const float4*)Ap;
        a1 = *(const float4*)(Ap + 4);
        b0 = *(const float4*)Bp;
        b1 = *(const float4*)(Bp + NDIM);
        uint4 u;
        u.x = pack_bf2(a0.x, a0.y); u.y = pack_bf2(a0.z, a0.w);
        u.z = pack_bf2(a1.x, a1.y); u.w = pack_bf2(a1.z, a1.w);
        *(uint4*)&As[0][aRow][aColP] = u;
        u.x = pack_bf2(b0.x, b1.x); u.y = pack_bf2(b0.y, b1.y);
        u.z = pack_bf2(b0.z, b1.z); u.w = pack_bf2(b0.w, b1.w);
        *(uint4*)&Bs[0][bR][bC] = u;
    }
    __syncthreads();

    for (int ks = 0; ks < NK; ks++) {
        int buf = ks & 1;
        if (ks + 1 < NK) {
            const float* ap = Ap + (ks + 1) * 16;
            a0 = *(const float4*)ap;
            a1 = *(const float4*)(ap + 4);
            const float* bp = Bp + (size_t)(ks + 1) * 16 * NDIM;
            b0 = *(const float4*)bp;
            b1 = *(const float4*)(bp + NDIM);
        }
        // compute on buf: one k16 step
        {
            unsigned af[2][4];
#pragma unroll
            for (int mt = 0; mt < 2; mt++) {
                int r = wm * 32 + mt * 16 + gid;
                af[mt][0] = As[buf][r][tig];
                af[mt][1] = As[buf][r + 8][tig];
                af[mt][2] = As[buf][r][tig + 4];
                af[mt][3] = As[buf][r + 8][tig + 4];
            }
#pragma unroll
            for (int nt = 0; nt < 8; nt++) {
                int cb = wn * 64 + nt * 8 + gid;
                unsigned bf0 = Bs[buf][tig][cb];
                unsigned bf1 = Bs[buf][tig + 4][cb];
#pragma unroll
                for (int mt = 0; mt < 2; mt++) {
                    asm volatile(
                        "mma.sync.aligned.m16n8k16.row.col.f32.bf16.bf16.f32 "
                        "{%0,%1,%2,%3},{%4,%5,%6,%7},{%8,%9},{%0,%1,%2,%3};"
                        : "+f"(acc[mt][nt][0]), "+f"(acc[mt][nt][1]),
                          "+f"(acc[mt][nt][2]), "+f"(acc[mt][nt][3])
                        : "r"(af[mt][0]), "r"(af[mt][1]), "r"(af[mt][2]), "r"(af[mt][3]),
                          "r"(bf0), "r"(bf1));
                }
            }
        }
        if (ks + 1 < NK) {
            int nb = (ks + 1) & 1;
            uint4 u;
            u.x = pack_bf2(a0.x, a0.y); u.y = pack_bf2(a0.z, a0.w);
            u.z = pack_bf2(a1.x, a1.y); u.w = pack_bf2(a1.z, a1.w);
            *(uint4*)&As[nb][aRow][aColP] = u;
            u.x = pack_bf2(b0.x, b1.x); u.y = pack_bf2(b0.y, b1.y);
            u.z = pack_bf2(b0.z, b1.z); u.w = pack_bf2(b0.w, b1.w);
            *(uint4*)&Bs[nb][bR][bC] = u;
        }
        __syncthreads();
    }

    // epilogue
#pragma unroll
    for (int mt = 0; mt < 2; mt++) {
#pragma unroll
        for (int nt = 0; nt < 8; nt++) {
            int r0 = m0 + wm * 32 + mt * 16 + gid;
            int c = n0 + wn * 64 + nt * 8 + 2 * tig;
            float bv0 = __ldg(bias + c), bv1 = __ldg(bias + c + 1);
            if (EPI == 0) {
                float v0 = acc[mt][nt][0] + bv0, v1 = acc[mt][nt][1] + bv1;
                float v2 = acc[mt][nt][2] + bv0, v3 = acc[mt][nt][3] + bv1;
                float2 w0 = make_float2(v0 * normcdff(v0), v1 * normcdff(v1));
                float2 w1 = make_float2(v2 * normcdff(v2), v3 * normcdff(v3));
                *(float2*)&g_mlp[(size_t)r0 * 512 + c] = w0;
                *(float2*)&g_mlp[(size_t)(r0 + 8) * 512 + c] = w1;
            } else {
#pragma unroll
                for (int half = 0; half < 2; half++) {
                    int row = r0 + half * 8;
                    int bb = row / 5120;
                    int lpp = row - bb * 5120;
                    int ll = lpp >> 10;
                    int pp = lpp & 1023;
                    float* orow = out + ((size_t)(bb * 6 + ll + 1) * 1024 + pp) * 256 + c;
                    float2 cur = *(float2*)orow;
                    cur.x += acc[mt][nt][half * 2 + 0] + bv0;
                    cur.y += acc[mt][nt][half * 2 + 1] + bv1;
                    *(float2*)orow = cur;
                }
            }
        }
    }
}

// ---------------- launch ----------------
extern "C" void kernel_launch(void* const* d_in, const int* in_sizes, int n_in,
                              void* d_out, int out_size) {
    const float* x    = (const float*)d_in[0];
    const float* ref  = (const float*)d_in[1];
    const float* n1g = (const float*)d_in[7];
    const float* n1b = (const float*)d_in[8];
    const float* awW = (const float*)d_in[9];
    const float* awb = (const float*)d_in[10];
    const float* soW = (const float*)d_in[11];
    const float* sob = (const float*)d_in[12];
    const float* n2g  = (const float*)d_in[23];
    const float* n2b  = (const float*)d_in[24];
    const float* fc1W = (const float*)d_in[25];
    const float* fc1b = (const float*)d_in[26];
    const float* fc2W = (const float*)d_in[27];
    const float* fc2b = (const float*)d_in[28];
    float* out = (float*)d_out;

    ProjParams P;
    for (int lvl = 0; lvl < 5; lvl++) {
        P.feat[lvl] = (const float*)d_in[2 + lvl];
        P.W[lvl]    = (const float*)d_in[13 + 2 * lvl];
        P.bias[lvl] = (const float*)d_in[14 + 2 * lvl];
    }

    proj_all<<<1376, 256>>>(P);
    copy_x0_kernel<<<1024, 256>>>(x, out);
    token_fused<<<2560, 256>>>(x, ref, n1g, n1b, awW, awb, soW, sob, n2g, n2b, out);
    mma_gemm<256, 512, 0><<<dim3(4, 160), 256>>>(fc1W, fc1b, out);
    mma_gemm<512, 256, 1><<<dim3(2, 160), 256>>>(fc2W, fc2b, out);
}

// round 5
// speedup vs baseline: 2.3290x; 1.0300x over previous
#include <cuda_runtime.h>
#include <cuda_bf16.h>
#include <math.h>

// ---------------- scratch (static device globals; no allocation) ----------------
static __device__ __align__(16) float g_pfeat[2818048];
static __device__ __align__(16) __nv_bfloat16 g_h2b[20480 * 256];
static __device__ __align__(16) __nv_bfloat16 g_mlpb[20480 * 512];
static __device__ __align__(16) unsigned g_w1[128 * 512];   // fc1_W packed (k-pair, col)
static __device__ __align__(16) unsigned g_w2[256 * 256];   // fc2_W packed (k-pair, col)

__device__ __forceinline__ unsigned pack_bf2(float lo, float hi) {
    __nv_bfloat162 h = __floats2bfloat162_rn(lo, hi);
    return *(unsigned*)&h;
}

// ---------------- pre-pack MLP weights to bf16 (k-pair interleaved) ----------------
__global__ void convert_w(const float* __restrict__ fc1W, const float* __restrict__ fc2W) {
    int i = blockIdx.x * blockDim.x + threadIdx.x;    // 0..131071
    if (i < 65536) {
        int kp = i >> 9, n = i & 511;                 // fc1: K=256,N=512
        g_w1[i] = pack_bf2(fc1W[(2 * kp) * 512 + n], fc1W[(2 * kp + 1) * 512 + n]);
    } else {
        int j = i - 65536;
        int kp = j >> 8, n = j & 255;                 // fc2: K=512,N=256
        g_w2[j] = pack_bf2(fc2W[(2 * kp) * 256 + n], fc2W[(2 * kp + 1) * 256 + n]);
    }
}

// ---------------- merged feature projection: one launch, all 5 levels ----------------
struct ProjParams {
    const float* feat[5];
    const float* W[5];
    const float* bias[5];
};

__global__ __launch_bounds__(256) void proj_all(ProjParams P) {
    const int starts[6] = {0, 1024, 1280, 1344, 1360, 1376};
    const int Cs[5]   = {64, 128, 256, 512, 256};
    const int HWs[5]  = {16384, 4096, 1024, 256, 256};
    const int offs[5] = {0, 2097152, 2621440, 2752512, 2785280};

    __shared__ float featS[32][64];
    __shared__ float WS[32][32];

    int blk = blockIdx.x;
    int l = 0;
#pragma unroll
    for (int i = 0; i < 4; i++) if (blk >= starts[l + 1]) l++;
    int tile = blk - starts[l];
    int C = Cs[l], HW = HWs[l];
    int pixbase = tile * 64;
    int b = pixbase / HW;
    int idx0 = pixbase - b * HW;

    const float* feat = P.feat[l];
    const float* Wp = P.W[l];
    const float* bp = P.bias[l];

    int t = threadIdx.x;
    int px = t & 63, grp = t >> 6;

    float acc[8];
#pragma unroll
    for (int j = 0; j < 8; j++) acc[j] = bp[grp * 8 + j];

    size_t fbase = ((size_t)b * C) * HW + idx0;

    for (int c0 = 0; c0 < C; c0 += 32) {
        __syncthreads();
#pragma unroll
        for (int k = 0; k < 8; k++) {
            int j = t + k * 256;
            int cc = j >> 6, pp = j & 63;
            featS[cc][pp] = feat[fbase + (size_t)(c0 + cc) * HW + pp];
        }
#pragma unroll
        for (int k = 0; k < 4; k++) {
            int j = t + k * 256;
            WS[j >> 5][j & 31] = Wp[(size_t)(c0 + (j >> 5)) * 32 + (j & 31)];
        }
        __syncthreads();
#pragma unroll
        for (int cc = 0; cc < 32; cc++) {
            float fv = featS[cc][px];
#pragma unroll
            for (int j = 0; j < 8; j++)
                acc[j] = fmaf(fv, WS[cc][grp * 8 + j], acc[j]);
        }
    }
    float* o = g_pfeat + offs[l] + (size_t)(pixbase + px) * 32 + grp * 8;
    *(float4*)o = make_float4(acc[0], acc[1], acc[2], acc[3]);
    *(float4*)(o + 4) = make_float4(acc[4], acc[5], acc[6], acc[7]);
}

// ---------------- copy x0 token slice to output ----------------
__global__ void copy_x0_kernel(const float* __restrict__ x, float* __restrict__ out) {
    int i = blockIdx.x * blockDim.x + threadIdx.x;
    int b = i >> 16;
    int r = i & 65535;
    const float4* xi = (const float4*)x;
    float4* oo = (float4*)out;
    size_t off = (size_t)b * (6 * 65536) + r;
    oo[off] = xi[off];
}

// ---------------- fused token kernel: 8 tokens per block, 256 threads ----------------
__global__ __launch_bounds__(256) void token_fused(
    const float* __restrict__ x, const float* __restrict__ ref,
    const float* __restrict__ n1g, const float* __restrict__ n1b,
    const float* __restrict__ awW, const float* __restrict__ awb,
    const float* __restrict__ soW, const float* __restrict__ sob,
    const float* __restrict__ n2g, const float* __restrict__ n2b,
    float* __restrict__ out) {
    __shared__ float h_sh[8][256];
    __shared__ float logit_sh[8][96];
    __shared__ float aw_sh[8][32];
    __shared__ float pos_sh[8][64];
    __shared__ float samp_sh[8][32 * 33];

    int t = threadIdx.x, lane = t & 31, w = t >> 5;
    int m0 = blockIdx.x * 8;
    int b = m0 / 5120;
    int lp = m0 - b * 5120;
    int l = lp >> 10;
    int p0 = lp & 1023;
    size_t base_q = ((size_t)(b * 6 + l + 1) * 1024 + p0) * 256;
    size_t base_0 = ((size_t)(b * 6) * 1024 + p0) * 256;

    // ---- P1: LN1, warp w handles token w ----
    {
        size_t xq_off = base_q + (size_t)w * 256;
        size_t x0_off = base_0 + (size_t)w * 256;
        float sv[8];
        float s = 0.0f;
#pragma unroll
        for (int i = 0; i < 8; i++) {
            int c = lane + 32 * i;
            sv[i] = x[xq_off + c] + x[x0_off + c];
            s += sv[i];
        }
#pragma unroll
        for (int o = 16; o > 0; o >>= 1) s += __shfl_xor_sync(0xffffffffu, s, o);
        float mean = s * (1.0f / 256.0f);
        float v = 0.0f;
#pragma unroll
        for (int i = 0; i < 8; i++) { float d = sv[i] - mean; v += d * d; }
#pragma unroll
        for (int o = 16; o > 0; o >>= 1) v += __shfl_xor_sync(0xffffffffu, v, o);
        float rstd = rsqrtf(v * (1.0f / 256.0f) + 1e-5f);
#pragma unroll
        for (int i = 0; i < 8; i++) {
            int c = lane + 32 * i;
            h_sh[w][c] = (sv[i] - mean) * rstd * n1g[c] + n1b[c];
        }
    }
    __syncthreads();

    // ---- P2: head logits ----
    if (t < 192) {
        int tok = t / 24;
        int jj = (t - tok * 24) * 4;
        const float* wcol;
        int stride;
        float a0, a1, a2, a3;
        if (jj < 32) {
            wcol = awW + jj; stride = 32;
            a0 = awb[jj]; a1 = awb[jj + 1]; a2 = awb[jj + 2]; a3 = awb[jj + 3];
        } else {
            wcol = soW + (jj - 32); stride = 64;
            a0 = sob[jj - 32]; a1 = sob[jj - 31]; a2 = sob[jj - 30]; a3 = sob[jj - 29];
        }
        const float* hrow = h_sh[tok];
#pragma unroll 8
        for (int k = 0; k < 256; k++) {
            float hv = hrow[k];
            float4 w4 = *(const float4*)(wcol + (size_t)k * stride);
            a0 = fmaf(hv, w4.x, a0);
            a1 = fmaf(hv, w4.y, a1);
            a2 = fmaf(hv, w4.z, a2);
            a3 = fmaf(hv, w4.w, a3);
        }
        logit_sh[tok][jj + 0] = a0;
        logit_sh[tok][jj + 1] = a1;
        logit_sh[tok][jj + 2] = a2;
        logit_sh[tok][jj + 3] = a3;
    }
    __syncthreads();

    // ---- P3: softmax + tanh positions ----
    if (t < 64) {
        int tok = t >> 3, hd = t & 7;
        float v0 = logit_sh[tok][hd * 4 + 0], v1 = logit_sh[tok][hd * 4 + 1];
        float v2 = logit_sh[tok][hd * 4 + 2], v3 = logit_sh[tok][hd * 4 + 3];
        float mx = fmaxf(fmaxf(v0, v1), fmaxf(v2, v3));
        float e0 = expf(v0 - mx), e1 = expf(v1 - mx), e2 = expf(v2 - mx), e3 = expf(v3 - mx);
        float inv = 1.0f / (e0 + e1 + e2 + e3);
        aw_sh[tok][hd * 4 + 0] = e0 * inv;
        aw_sh[tok][hd * 4 + 1] = e1 * inv;
        aw_sh[tok][hd * 4 + 2] = e2 * inv;
        aw_sh[tok][hd * 4 + 3] = e3 * inv;
    }
#pragma unroll
    for (int i = 0; i < 2; i++) {
        int o = t + 256 * i;
        int tok = o >> 6, j = o & 63;
        pos_sh[tok][j] = tanhf(logit_sh[tok][32 + j]) +
                         ref[((size_t)b * 1024 + p0 + tok) * 2 + (j & 1)];
    }
    __syncthreads();

    // ---- P4: bilinear sampling ----
    {
        const int lvlW_[5] = {128, 64, 32, 16, 16};
        const int lvlOff_[5] = {0, 2097152, 2621440, 2752512, 2785280};
        int tok = t >> 5, q = lane;
        int W = lvlW_[l];
        float fw = (float)(W - 1);
        float gx = fminf(fmaxf((pos_sh[tok][2 * q + 0] + 1.0f) * 0.5f * fw, 0.0f), fw);
        float gy = fminf(fmaxf((pos_sh[tok][2 * q + 1] + 1.0f) * 0.5f * fw, 0.0f), fw);
        float x0f = floorf(gx), y0f = floorf(gy);
        float wx = gx - x0f, wy = gy - y0f;
        int x0i = (int)x0f, y0i = (int)y0f;
        int x1i = min(x0i + 1, W - 1), y1i = min(y0i + 1, W - 1);
        const float* bb = g_pfeat + lvlOff_[l] + (size_t)b * W * W * 32;
        const float* p00 = bb + (size_t)(y0i * W + x0i) * 32;
        const float* p01 = bb + (size_t)(y0i * W + x1i) * 32;
        const float* p10 = bb + (size_t)(y1i * W + x0i) * 32;
        const float* p11 = bb + (size_t)(y1i * W + x1i) * 32;
        float a = aw_sh[tok][q];
        float aw00 = a * (1.0f - wx) * (1.0f - wy);
        float aw01 = a * wx * (1.0f - wy);
        float aw10 = a * (1.0f - wx) * wy;
        float aw11 = a * wx * wy;
        float* dst = &samp_sh[tok][q * 33];
#pragma unroll
        for (int c4 = 0; c4 < 32; c4 += 4) {
            float4 f00 = *(const float4*)(p00 + c4);
            float4 f01 = *(const float4*)(p01 + c4);
            float4 f10 = *(const float4*)(p10 + c4);
            float4 f11 = *(const float4*)(p11 + c4);
            dst[c4 + 0] = aw00 * f00.x + aw01 * f01.x + aw10 * f10.x + aw11 * f11.x;
            dst[c4 + 1] = aw00 * f00.y + aw01 * f01.y + aw10 * f10.y + aw11 * f11.y;
            dst[c4 + 2] = aw00 * f00.z + aw01 * f01.z + aw10 * f10.z + aw11 * f11.z;
            dst[c4 + 3] = aw00 * f00.w + aw01 * f01.w + aw10 * f10.w + aw11 * f11.w;
        }
    }
    __syncthreads();

    // ---- P5: head combine + residual + LN2 -> bf16 h2 ----
    {
        size_t xq_off = base_q + (size_t)w * 256;
        float o8[8];
        float s = 0.0f;
#pragma unroll
        for (int i = 0; i < 8; i++) {
            int c = lane + 32 * i;
            int hq = i * 4;
            float ov = samp_sh[w][(hq + 0) * 33 + lane] + samp_sh[w][(hq + 1) * 33 + lane] +
                       samp_sh[w][(hq + 2) * 33 + lane] + samp_sh[w][(hq + 3) * 33 + lane];
            float xq2 = x[xq_off + c] + ov;
            out[xq_off + c] = xq2;
            o8[i] = xq2;
            s += xq2;
        }
#pragma unroll
        for (int o = 16; o > 0; o >>= 1) s += __shfl_xor_sync(0xffffffffu, s, o);
        float mean = s * (1.0f / 256.0f);
        float v = 0.0f;
#pragma unroll
        for (int i = 0; i < 8; i++) { float d = o8[i] - mean; v += d * d; }
#pragma unroll
        for (int o = 16; o > 0; o >>= 1) v += __shfl_xor_sync(0xffffffffu, v, o);
        float rstd = rsqrtf(v * (1.0f / 256.0f) + 1e-5f);
#pragma unroll
        for (int i = 0; i < 8; i++) {
            int c = lane + 32 * i;
            g_h2b[(size_t)(m0 + w) * 256 + c] =
                __float2bfloat16((o8[i] - mean) * rstd * n2g[c] + n2b[c]);
        }
    }
}

// ---------------- bf16 tensor-core GEMM (m16n8k16, fp32 accumulate) ----------------
// A, B already bf16; B pre-packed (k-pair, col). Pure copy into smem, no cvt.
//   EPI=0: A=g_h2b  (K=256, N=512) -> g_mlpb = gelu(.)  (bf16)
//   EPI=1: A=g_mlpb (K=512, N=256) -> out[token scatter] += .
template <int K, int NDIM, int EPI>
__global__ __launch_bounds__(256, 2) void mma_gemm(const float* __restrict__ bias,
                                                   float* __restrict__ out) {
    const unsigned* A = (EPI == 0) ? (const unsigned*)g_h2b : (const unsigned*)g_mlpb;
    const unsigned* Bpk = (EPI == 0) ? g_w1 : g_w2;
    const int KW = K / 2;                 // packed words per A row

    __shared__ unsigned As[2][128][12];   // [row][kp], pad 12
    __shared__ unsigned Bs[2][8][136];    // [kp][col], pad 136

    int tid = threadIdx.x;
    int m0 = blockIdx.y * 128, n0 = blockIdx.x * 128;

    int aRow = tid >> 1, aColP = (tid & 1) * 4;
    int bR = tid >> 5;
    int bC = (tid & 31) * 4;
    const unsigned* Ap = A + (size_t)(m0 + aRow) * KW + aColP;
    const unsigned* Bp = Bpk + (size_t)bR * NDIM + n0 + bC;

    int lane = tid & 31, wid = tid >> 5;
    int wm = wid & 3, wn = wid >> 2;
    int gid = lane >> 2, tig = lane & 3;

    float acc[2][8][4];
#pragma unroll
    for (int mt = 0; mt < 2; mt++)
#pragma unroll
        for (int nt = 0; nt < 8; nt++)
#pragma unroll
            for (int r = 0; r < 4; r++) acc[mt][nt][r] = 0.0f;

    uint4 av, bv;
    const int NK = K / 16;

    // prologue
    av = *(const uint4*)Ap;
    bv = *(const uint4*)Bp;
    *(uint4*)&As[0][aRow][aColP] = av;
    *(uint4*)&Bs[0][bR][bC] = bv;
    __syncthreads();

    for (int ks = 0; ks < NK; ks++) {
        int buf = ks & 1;
        if (ks + 1 < NK) {
            av = *(const uint4*)(Ap + (ks + 1) * 8);
            bv = *(const uint4*)(Bp + (size_t)(ks + 1) * 8 * NDIM);
        }
        {
            unsigned af[2][4];
#pragma unroll
            for (int mt = 0; mt < 2; mt++) {
                int r = wm * 32 + mt * 16 + gid;
                af[mt][0] = As[buf][r][tig];
                af[mt][1] = As[buf][r + 8][tig];
                af[mt][2] = As[buf][r][tig + 4];
                af[mt][3] = As[buf][r + 8][tig + 4];
            }
#pragma unroll
            for (int nt = 0; nt < 8; nt++) {
                int cb = wn * 64 + nt * 8 + gid;
                unsigned bf0 = Bs[buf][tig][cb];
                unsigned bf1 = Bs[buf][tig + 4][cb];
#pragma unroll
                for (int mt = 0; mt < 2; mt++) {
                    asm volatile(
                        "mma.sync.aligned.m16n8k16.row.col.f32.bf16.bf16.f32 "
                        "{%0,%1,%2,%3},{%4,%5,%6,%7},{%8,%9},{%0,%1,%2,%3};"
                        : "+f"(acc[mt][nt][0]), "+f"(acc[mt][nt][1]),
                          "+f"(acc[mt][nt][2]), "+f"(acc[mt][nt][3])
                        : "r"(af[mt][0]), "r"(af[mt][1]), "r"(af[mt][2]), "r"(af[mt][3]),
                          "r"(bf0), "r"(bf1));
                }
            }
        }
        if (ks + 1 < NK) {
            int nb = (ks + 1) & 1;
            *(uint4*)&As[nb][aRow][aColP] = av;
            *(uint4*)&Bs[nb][bR][bC] = bv;
        }
        __syncthreads();
    }

    // epilogue
#pragma unroll
    for (int mt = 0; mt < 2; mt++) {
#pragma unroll
        for (int nt = 0; nt < 8; nt++) {
            int r0 = m0 + wm * 32 + mt * 16 + gid;
            int c = n0 + wn * 64 + nt * 8 + 2 * tig;
            float bv0 = __ldg(bias + c), bv1 = __ldg(bias + c + 1);
            if (EPI == 0) {
                float v0 = acc[mt][nt][0] + bv0, v1 = acc[mt][nt][1] + bv1;
                float v2 = acc[mt][nt][2] + bv0, v3 = acc[mt][nt][3] + bv1;
                unsigned* gm = (unsigned*)g_mlpb;
                gm[((size_t)r0 * 512 + c) >> 1] = pack_bf2(v0 * normcdff(v0), v1 * normcdff(v1));
                gm[((size_t)(r0 + 8) * 512 + c) >> 1] = pack_bf2(v2 * normcdff(v2), v3 * normcdff(v3));
            } else {
#pragma unroll
                for (int half = 0; half < 2; half++) {
                    int row = r0 + half * 8;
                    int bb = row / 5120;
                    int lpp = row - bb * 5120;
                    int ll = lpp >> 10;
                    int pp = lpp & 1023;
                    float* orow = out + ((size_t)(bb * 6 + ll + 1) * 1024 + pp) * 256 + c;
                    float2 cur = *(float2*)orow;
                    cur.x += acc[mt][nt][half * 2 + 0] + bv0;
                    cur.y += acc[mt][nt][half * 2 + 1] + bv1;
                    *(float2*)orow = cur;
                }
            }
        }
    }
}

// ---------------- launch ----------------
extern "C" void kernel_launch(void* const* d_in, const int* in_sizes, int n_in,
                              void* d_out, int out_size) {
    const float* x    = (const float*)d_in[0];
    const float* ref  = (const float*)d_in[1];
    const float* n1g = (const float*)d_in[7];
    const float* n1b = (const float*)d_in[8];
    const float* awW = (const float*)d_in[9];
    const float* awb = (const float*)d_in[10];
    const float* soW = (const float*)d_in[11];
    const float* sob = (const float*)d_in[12];
    const float* n2g  = (const float*)d_in[23];
    const float* n2b  = (const float*)d_in[24];
    const float* fc1W = (const float*)d_in[25];
    const float* fc1b = (const float*)d_in[26];
    const float* fc2W = (const float*)d_in[27];
    const float* fc2b = (const float*)d_in[28];
    float* out = (float*)d_out;

    ProjParams P;
    for (int lvl = 0; lvl < 5; lvl++) {
        P.feat[lvl] = (const float*)d_in[2 + lvl];
        P.W[lvl]    = (const float*)d_in[13 + 2 * lvl];
        P.bias[lvl] = (const float*)d_in[14 + 2 * lvl];
    }

    convert_w<<<512, 256>>>(fc1W, fc2W);
    proj_all<<<1376, 256>>>(P);
    copy_x0_kernel<<<1024, 256>>>(x, out);
    token_fused<<<2560, 256>>>(x, ref, n1g, n1b, awW, awb, soW, sob, n2g, n2b, out);
    mma_gemm<256, 512, 0><<<dim3(4, 160), 256>>>(fc1b, out);
    mma_gemm<512, 256, 1><<<dim3(2, 160), 256>>>(fc2b, out);
}

// round 6
// speedup vs baseline: 2.5263x; 1.0847x over previous
#include <cuda_runtime.h>
#include <cuda_bf16.h>
#include <math.h>

// ---------------- scratch (static device globals; no allocation) ----------------
static __device__ __align__(16) float g_pfeat[2818048];
static __device__ __align__(16) __nv_bfloat16 g_h2b[20480 * 256];
static __device__ __align__(16) __nv_bfloat16 g_mlpb[20480 * 512];
static __device__ __align__(16) unsigned g_w1[128 * 512];   // fc1_W packed (k-pair, col)
static __device__ __align__(16) unsigned g_w2[256 * 256];   // fc2_W packed (k-pair, col)

__device__ __forceinline__ unsigned pack_bf2(float lo, float hi) {
    __nv_bfloat162 h = __floats2bfloat162_rn(lo, hi);
    return *(unsigned*)&h;
}

// ---------------- pre-pack MLP weights to bf16 (k-pair interleaved) ----------------
__global__ void convert_w(const float* __restrict__ fc1W, const float* __restrict__ fc2W) {
    int i = blockIdx.x * blockDim.x + threadIdx.x;    // 0..131071
    if (i < 65536) {
        int kp = i >> 9, n = i & 511;                 // fc1: K=256,N=512
        g_w1[i] = pack_bf2(fc1W[(2 * kp) * 512 + n], fc1W[(2 * kp + 1) * 512 + n]);
    } else {
        int j = i - 65536;
        int kp = j >> 8, n = j & 255;                 // fc2: K=512,N=256
        g_w2[j] = pack_bf2(fc2W[(2 * kp) * 256 + n], fc2W[(2 * kp + 1) * 256 + n]);
    }
}

// ---------------- merged feature projection: one launch, all 5 levels ----------------
struct ProjParams {
    const float* feat[5];
    const float* W[5];
    const float* bias[5];
};

__global__ __launch_bounds__(256) void proj_all(ProjParams P) {
    const int starts[6] = {0, 1024, 1280, 1344, 1360, 1376};
    const int Cs[5]   = {64, 128, 256, 512, 256};
    const int HWs[5]  = {16384, 4096, 1024, 256, 256};
    const int offs[5] = {0, 2097152, 2621440, 2752512, 2785280};

    __shared__ float featS[32][64];
    __shared__ float WS[32][32];

    int blk = blockIdx.x;
    int l = 0;
#pragma unroll
    for (int i = 0; i < 4; i++) if (blk >= starts[l + 1]) l++;
    int tile = blk - starts[l];
    int C = Cs[l], HW = HWs[l];
    int pixbase = tile * 64;
    int b = pixbase / HW;
    int idx0 = pixbase - b * HW;

    const float* feat = P.feat[l];
    const float* Wp = P.W[l];
    const float* bp = P.bias[l];

    int t = threadIdx.x;
    int px = t & 63, grp = t >> 6;

    float acc[8];
#pragma unroll
    for (int j = 0; j < 8; j++) acc[j] = bp[grp * 8 + j];

    size_t fbase = ((size_t)b * C) * HW + idx0;

    for (int c0 = 0; c0 < C; c0 += 32) {
        __syncthreads();
#pragma unroll
        for (int k = 0; k < 8; k++) {
            int j = t + k * 256;
            int cc = j >> 6, pp = j & 63;
            featS[cc][pp] = feat[fbase + (size_t)(c0 + cc) * HW + pp];
        }
#pragma unroll
        for (int k = 0; k < 4; k++) {
            int j = t + k * 256;
            WS[j >> 5][j & 31] = Wp[(size_t)(c0 + (j >> 5)) * 32 + (j & 31)];
        }
        __syncthreads();
#pragma unroll
        for (int cc = 0; cc < 32; cc++) {
            float fv = featS[cc][px];
#pragma unroll
            for (int j = 0; j < 8; j++)
                acc[j] = fmaf(fv, WS[cc][grp * 8 + j], acc[j]);
        }
    }
    float* o = g_pfeat + offs[l] + (size_t)(pixbase + px) * 32 + grp * 8;
    *(float4*)o = make_float4(acc[0], acc[1], acc[2], acc[3]);
    *(float4*)(o + 4) = make_float4(acc[4], acc[5], acc[6], acc[7]);
}

// ---------------- copy x0 token slice to output ----------------
__global__ void copy_x0_kernel(const float* __restrict__ x, float* __restrict__ out) {
    int i = blockIdx.x * blockDim.x + threadIdx.x;
    int b = i >> 16;
    int r = i & 65535;
    const float4* xi = (const float4*)x;
    float4* oo = (float4*)out;
    size_t off = (size_t)b * (6 * 65536) + r;
    oo[off] = xi[off];
}

// ---------------- fused token kernel: 8 tokens per block, 256 threads ----------------
__global__ __launch_bounds__(256) void token_fused(
    const float* __restrict__ x, const float* __restrict__ ref,
    const float* __restrict__ n1g, const float* __restrict__ n1b,
    const float* __restrict__ awW, const float* __restrict__ awb,
    const float* __restrict__ soW, const float* __restrict__ sob,
    const float* __restrict__ n2g, const float* __restrict__ n2b,
    float* __restrict__ out) {
    __shared__ float h_sh[8][256];        // 8KB
    __shared__ float logit_sh[8][96];     // 3KB
    __shared__ float aw_sh[8][32];        // 1KB
    __shared__ int   tap_sh[8][32][4];    // 4KB : tap float-offsets into level base
    __shared__ float wgt_sh[8][32][4];    // 4KB : attention*bilinear weights
    __shared__ float o_sh[8][256];        // 8KB : per-token attention output

    int t = threadIdx.x, lane = t & 31, w = t >> 5;
    int m0 = blockIdx.x * 8;
    int b = m0 / 5120;
    int lp = m0 - b * 5120;
    int l = lp >> 10;
    int p0 = lp & 1023;
    size_t base_q = ((size_t)(b * 6 + l + 1) * 1024 + p0) * 256;
    size_t base_0 = ((size_t)(b * 6) * 1024 + p0) * 256;

    const int lvlW_[5] = {128, 64, 32, 16, 16};
    const int lvlOff_[5] = {0, 2097152, 2621440, 2752512, 2785280};
    const int W = lvlW_[l];
    const float* lvlbase = g_pfeat + lvlOff_[l] + (size_t)b * W * W * 32;

    // ---- P1: LN1, warp w handles token w ----
    {
        size_t xq_off = base_q + (size_t)w * 256;
        size_t x0_off = base_0 + (size_t)w * 256;
        float sv[8];
        float s = 0.0f;
#pragma unroll
        for (int i = 0; i < 8; i++) {
            int c = lane + 32 * i;
            sv[i] = x[xq_off + c] + x[x0_off + c];
            s += sv[i];
        }
#pragma unroll
        for (int o = 16; o > 0; o >>= 1) s += __shfl_xor_sync(0xffffffffu, s, o);
        float mean = s * (1.0f / 256.0f);
        float v = 0.0f;
#pragma unroll
        for (int i = 0; i < 8; i++) { float d = sv[i] - mean; v += d * d; }
#pragma unroll
        for (int o = 16; o > 0; o >>= 1) v += __shfl_xor_sync(0xffffffffu, v, o);
        float rstd = rsqrtf(v * (1.0f / 256.0f) + 1e-5f);
#pragma unroll
        for (int i = 0; i < 8; i++) {
            int c = lane + 32 * i;
            h_sh[w][c] = (sv[i] - mean) * rstd * n1g[c] + n1b[c];
        }
    }
    __syncthreads();

    // ---- P2: head logits, 8 tok x 96 cols; thread handles 4 adjacent cols ----
    if (t < 192) {
        int tok = t / 24;
        int jj = (t - tok * 24) * 4;
        const float* wcol;
        int stride;
        float a0, a1, a2, a3;
        if (jj < 32) {
            wcol = awW + jj; stride = 32;
            a0 = awb[jj]; a1 = awb[jj + 1]; a2 = awb[jj + 2]; a3 = awb[jj + 3];
        } else {
            wcol = soW + (jj - 32); stride = 64;
            a0 = sob[jj - 32]; a1 = sob[jj - 31]; a2 = sob[jj - 30]; a3 = sob[jj - 29];
        }
        const float* hrow = h_sh[tok];
#pragma unroll 8
        for (int k = 0; k < 256; k++) {
            float hv = hrow[k];
            float4 w4 = *(const float4*)(wcol + (size_t)k * stride);
            a0 = fmaf(hv, w4.x, a0);
            a1 = fmaf(hv, w4.y, a1);
            a2 = fmaf(hv, w4.z, a2);
            a3 = fmaf(hv, w4.w, a3);
        }
        logit_sh[tok][jj + 0] = a0;
        logit_sh[tok][jj + 1] = a1;
        logit_sh[tok][jj + 2] = a2;
        logit_sh[tok][jj + 3] = a3;
    }
    __syncthreads();

    // ---- P3a: softmax over NS=4 per head (64 threads) ----
    if (t < 64) {
        int tok = t >> 3, hd = t & 7;
        float v0 = logit_sh[tok][hd * 4 + 0], v1 = logit_sh[tok][hd * 4 + 1];
        float v2 = logit_sh[tok][hd * 4 + 2], v3 = logit_sh[tok][hd * 4 + 3];
        float mx = fmaxf(fmaxf(v0, v1), fmaxf(v2, v3));
        float e0 = expf(v0 - mx), e1 = expf(v1 - mx), e2 = expf(v2 - mx), e3 = expf(v3 - mx);
        float inv = 1.0f / (e0 + e1 + e2 + e3);
        aw_sh[tok][hd * 4 + 0] = e0 * inv;
        aw_sh[tok][hd * 4 + 1] = e1 * inv;
        aw_sh[tok][hd * 4 + 2] = e2 * inv;
        aw_sh[tok][hd * 4 + 3] = e3 * inv;
    }
    __syncthreads();

    // ---- P3b: per (tok, q) compute taps + combined weights (256 threads exactly) ----
    {
        int tok = t >> 5, q = lane;
        float rx = ref[((size_t)b * 1024 + p0 + tok) * 2 + 0];
        float ry = ref[((size_t)b * 1024 + p0 + tok) * 2 + 1];
        float px_ = tanhf(logit_sh[tok][32 + 2 * q + 0]) + rx;
        float py_ = tanhf(logit_sh[tok][32 + 2 * q + 1]) + ry;
        float fw = (float)(W - 1);
        float gx = fminf(fmaxf((px_ + 1.0f) * 0.5f * fw, 0.0f), fw);
        float gy = fminf(fmaxf((py_ + 1.0f) * 0.5f * fw, 0.0f), fw);
        float x0f = floorf(gx), y0f = floorf(gy);
        float wx = gx - x0f, wy = gy - y0f;
        int x0i = (int)x0f, y0i = (int)y0f;
        int x1i = min(x0i + 1, W - 1), y1i = min(y0i + 1, W - 1);
        tap_sh[tok][q][0] = (y0i * W + x0i) * 32;
        tap_sh[tok][q][1] = (y0i * W + x1i) * 32;
        tap_sh[tok][q][2] = (y1i * W + x0i) * 32;
        tap_sh[tok][q][3] = (y1i * W + x1i) * 32;
        float a = aw_sh[tok][q];
        wgt_sh[tok][q][0] = a * (1.0f - wx) * (1.0f - wy);
        wgt_sh[tok][q][1] = a * wx * (1.0f - wy);
        wgt_sh[tok][q][2] = a * (1.0f - wx) * wy;
        wgt_sh[tok][q][3] = a * wx * wy;
    }
    __syncthreads();

    // ---- P4: coalesced gather + head accumulate ----
    // slot = (tok, head, cg): 8 consecutive threads (cg) read one 128B tap row.
#pragma unroll
    for (int iter = 0; iter < 2; iter++) {
        int slot = t + 256 * iter;           // 0..511
        int tok = slot >> 6;
        int head = (slot >> 3) & 7;
        int cg = (slot & 7) * 4;
        float ax = 0.0f, ay = 0.0f, az = 0.0f, aw4 = 0.0f;
#pragma unroll
        for (int s = 0; s < 4; s++) {
            int q = head * 4 + s;
            const int* tp = tap_sh[tok][q];
            const float* wt = wgt_sh[tok][q];
#pragma unroll
            for (int tap = 0; tap < 4; tap++) {
                float4 f = *(const float4*)(lvlbase + tp[tap] + cg);
                float wv = wt[tap];
                ax = fmaf(wv, f.x, ax);
                ay = fmaf(wv, f.y, ay);
                az = fmaf(wv, f.z, az);
                aw4 = fmaf(wv, f.w, aw4);
            }
        }
        *(float4*)&o_sh[tok][head * 32 + cg] = make_float4(ax, ay, az, aw4);
    }
    __syncthreads();

    // ---- P5: residual + LN2 -> bf16 h2 (warp w = token w) ----
    {
        size_t xq_off = base_q + (size_t)w * 256;
        float o8[8];
        float s = 0.0f;
#pragma unroll
        for (int i = 0; i < 8; i++) {
            int c = lane + 32 * i;
            float xq2 = x[xq_off + c] + o_sh[w][c];
            out[xq_off + c] = xq2;
            o8[i] = xq2;
            s += xq2;
        }
#pragma unroll
        for (int o = 16; o > 0; o >>= 1) s += __shfl_xor_sync(0xffffffffu, s, o);
        float mean = s * (1.0f / 256.0f);
        float v = 0.0f;
#pragma unroll
        for (int i = 0; i < 8; i++) { float d = o8[i] - mean; v += d * d; }
#pragma unroll
        for (int o = 16; o > 0; o >>= 1) v += __shfl_xor_sync(0xffffffffu, v, o);
        float rstd = rsqrtf(v * (1.0f / 256.0f) + 1e-5f);
#pragma unroll
        for (int i = 0; i < 8; i++) {
            int c = lane + 32 * i;
            g_h2b[(size_t)(m0 + w) * 256 + c] =
                __float2bfloat16((o8[i] - mean) * rstd * n2g[c] + n2b[c]);
        }
    }
}

// ---------------- bf16 tensor-core GEMM (m16n8k16, fp32 accumulate) ----------------
template <int K, int NDIM, int EPI>
__global__ __launch_bounds__(256, 2) void mma_gemm(const float* __restrict__ bias,
                                                   float* __restrict__ out) {
    const unsigned* A = (EPI == 0) ? (const unsigned*)g_h2b : (const unsigned*)g_mlpb;
    const unsigned* Bpk = (EPI == 0) ? g_w1 : g_w2;
    const int KW = K / 2;

    __shared__ unsigned As[2][128][12];
    __shared__ unsigned Bs[2][8][136];

    int tid = threadIdx.x;
    int m0 = blockIdx.y * 128, n0 = blockIdx.x * 128;

    int aRow = tid >> 1, aColP = (tid & 1) * 4;
    int bR = tid >> 5;
    int bC = (tid & 31) * 4;
    const unsigned* Ap = A + (size_t)(m0 + aRow) * KW + aColP;
    const unsigned* Bp = Bpk + (size_t)bR * NDIM + n0 + bC;

    int lane = tid & 31, wid = tid >> 5;
    int wm = wid & 3, wn = wid >> 2;
    int gid = lane >> 2, tig = lane & 3;

    float acc[2][8][4];
#pragma unroll
    for (int mt = 0; mt < 2; mt++)
#pragma unroll
        for (int nt = 0; nt < 8; nt++)
#pragma unroll
            for (int r = 0; r < 4; r++) acc[mt][nt][r] = 0.0f;

    uint4 av, bv;
    const int NK = K / 16;

    av = *(const uint4*)Ap;
    bv = *(const uint4*)Bp;
    *(uint4*)&As[0][aRow][aColP] = av;
    *(uint4*)&Bs[0][bR][bC] = bv;
    __syncthreads();

    for (int ks = 0; ks < NK; ks++) {
        int buf = ks & 1;
        if (ks + 1 < NK) {
            av = *(const uint4*)(Ap + (ks + 1) * 8);
            bv = *(const uint4*)(Bp + (size_t)(ks + 1) * 8 * NDIM);
        }
        {
            unsigned af[2][4];
#pragma unroll
            for (int mt = 0; mt < 2; mt++) {
                int r = wm * 32 + mt * 16 + gid;
                af[mt][0] = As[buf][r][tig];
                af[mt][1] = As[buf][r + 8][tig];
                af[mt][2] = As[buf][r][tig + 4];
                af[mt][3] = As[buf][r + 8][tig + 4];
            }
#pragma unroll
            for (int nt = 0; nt < 8; nt++) {
                int cb = wn * 64 + nt * 8 + gid;
                unsigned bf0 = Bs[buf][tig][cb];
                unsigned bf1 = Bs[buf][tig + 4][cb];
#pragma unroll
                for (int mt = 0; mt < 2; mt++) {
                    asm volatile(
                        "mma.sync.aligned.m16n8k16.row.col.f32.bf16.bf16.f32 "
                        "{%0,%1,%2,%3},{%4,%5,%6,%7},{%8,%9},{%0,%1,%2,%3};"
                        : "+f"(acc[mt][nt][0]), "+f"(acc[mt][nt][1]),
                          "+f"(acc[mt][nt][2]), "+f"(acc[mt][nt][3])
                        : "r"(af[mt][0]), "r"(af[mt][1]), "r"(af[mt][2]), "r"(af[mt][3]),
                          "r"(bf0), "r"(bf1));
                }
            }
        }
        if (ks + 1 < NK) {
            int nb = (ks + 1) & 1;
            *(uint4*)&As[nb][aRow][aColP] = av;
            *(uint4*)&Bs[nb][bR][bC] = bv;
        }
        __syncthreads();
    }

#pragma unroll
    for (int mt = 0; mt < 2; mt++) {
#pragma unroll
        for (int nt = 0; nt < 8; nt++) {
            int r0 = m0 + wm * 32 + mt * 16 + gid;
            int c = n0 + wn * 64 + nt * 8 + 2 * tig;
            float bv0 = __ldg(bias + c), bv1 = __ldg(bias + c + 1);
            if (EPI == 0) {
                float v0 = acc[mt][nt][0] + bv0, v1 = acc[mt][nt][1] + bv1;
                float v2 = acc[mt][nt][2] + bv0, v3 = acc[mt][nt][3] + bv1;
                unsigned* gm = (unsigned*)g_mlpb;
                gm[((size_t)r0 * 512 + c) >> 1] = pack_bf2(v0 * normcdff(v0), v1 * normcdff(v1));
                gm[((size_t)(r0 + 8) * 512 + c) >> 1] = pack_bf2(v2 * normcdff(v2), v3 * normcdff(v3));
            } else {
#pragma unroll
                for (int half = 0; half < 2; half++) {
                    int row = r0 + half * 8;
                    int bb = row / 5120;
                    int lpp = row - bb * 5120;
                    int ll = lpp >> 10;
                    int pp = lpp & 1023;
                    float* orow = out + ((size_t)(bb * 6 + ll + 1) * 1024 + pp) * 256 + c;
                    float2 cur = *(float2*)orow;
                    cur.x += acc[mt][nt][half * 2 + 0] + bv0;
                    cur.y += acc[mt][nt][half * 2 + 1] + bv1;
                    *(float2*)orow = cur;
                }
            }
        }
    }
}

// ---------------- launch ----------------
extern "C" void kernel_launch(void* const* d_in, const int* in_sizes, int n_in,
                              void* d_out, int out_size) {
    const float* x    = (const float*)d_in[0];
    const float* ref  = (const float*)d_in[1];
    const float* n1g = (const float*)d_in[7];
    const float* n1b = (const float*)d_in[8];
    const float* awW = (const float*)d_in[9];
    const float* awb = (const float*)d_in[10];
    const float* soW = (const float*)d_in[11];
    const float* sob = (const float*)d_in[12];
    const float* n2g  = (const float*)d_in[23];
    const float* n2b  = (const float*)d_in[24];
    const float* fc1W = (const float*)d_in[25];
    const float* fc1b = (const float*)d_in[26];
    const float* fc2W = (const float*)d_in[27];
    const float* fc2b = (const float*)d_in[28];
    float* out = (float*)d_out;

    ProjParams P;
    for (int lvl = 0; lvl < 5; lvl++) {
        P.feat[lvl] = (const float*)d_in[2 + lvl];
        P.W[lvl]    = (const float*)d_in[13 + 2 * lvl];
        P.bias[lvl] = (const float*)d_in[14 + 2 * lvl];
    }

    convert_w<<<512, 256>>>(fc1W, fc2W);
    proj_all<<<1376, 256>>>(P);
    copy_x0_kernel<<<1024, 256>>>(x, out);
    token_fused<<<2560, 256>>>(x, ref, n1g, n1b, awW, awb, soW, sob, n2g, n2b, out);
    mma_gemm<256, 512, 0><<<dim3(4, 160), 256>>>(fc1b, out);
    mma_gemm<512, 256, 1><<<dim3(2, 160), 256>>>(fc2b, out);
}

// round 7
// speedup vs baseline: 2.7788x; 1.0999x over previous
#include <cuda_runtime.h>
#include <cuda_bf16.h>
#include <math.h>

// ---------------- scratch (static device globals; no allocation) ----------------
static __device__ __align__(16) float g_pfeat[2818048];
static __device__ __align__(16) __nv_bfloat16 g_h2b[20480 * 256];
static __device__ __align__(16) __nv_bfloat16 g_mlpb[20480 * 512];
static __device__ __align__(16) unsigned g_w1[128 * 512];   // fc1_W packed (k-pair, col)
static __device__ __align__(16) unsigned g_w2[256 * 256];   // fc2_W packed (k-pair, col)

__device__ __forceinline__ unsigned pack_bf2(float lo, float hi) {
    __nv_bfloat162 h = __floats2bfloat162_rn(lo, hi);
    return *(unsigned*)&h;
}

// ---------------- pre-pack MLP weights to bf16 (k-pair interleaved) ----------------
__global__ void convert_w(const float* __restrict__ fc1W, const float* __restrict__ fc2W) {
    int i = blockIdx.x * blockDim.x + threadIdx.x;    // 0..131071
    if (i < 65536) {
        int kp = i >> 9, n = i & 511;                 // fc1: K=256,N=512
        g_w1[i] = pack_bf2(fc1W[(2 * kp) * 512 + n], fc1W[(2 * kp + 1) * 512 + n]);
    } else {
        int j = i - 65536;
        int kp = j >> 8, n = j & 255;                 // fc2: K=512,N=256
        g_w2[j] = pack_bf2(fc2W[(2 * kp) * 256 + n], fc2W[(2 * kp + 1) * 256 + n]);
    }
}

// ---------------- merged feature projection: one launch, all 5 levels ----------------
struct ProjParams {
    const float* feat[5];
    const float* W[5];
    const float* bias[5];
};

__global__ __launch_bounds__(256) void proj_all(ProjParams P) {
    const int starts[6] = {0, 1024, 1280, 1344, 1360, 1376};
    const int Cs[5]   = {64, 128, 256, 512, 256};
    const int HWs[5]  = {16384, 4096, 1024, 256, 256};
    const int offs[5] = {0, 2097152, 2621440, 2752512, 2785280};

    __shared__ float featS[32][64];
    __shared__ float WS[32][32];

    int blk = blockIdx.x;
    int l = 0;
#pragma unroll
    for (int i = 0; i < 4; i++) if (blk >= starts[l + 1]) l++;
    int tile = blk - starts[l];
    int C = Cs[l], HW = HWs[l];
    int pixbase = tile * 64;
    int b = pixbase / HW;
    int idx0 = pixbase - b * HW;

    const float* feat = P.feat[l];
    const float* Wp = P.W[l];
    const float* bp = P.bias[l];

    int t = threadIdx.x;
    int px = t & 63, grp = t >> 6;

    float acc[8];
#pragma unroll
    for (int j = 0; j < 8; j++) acc[j] = bp[grp * 8 + j];

    size_t fbase = ((size_t)b * C) * HW + idx0;

    for (int c0 = 0; c0 < C; c0 += 32) {
        __syncthreads();
#pragma unroll
        for (int k = 0; k < 8; k++) {
            int j = t + k * 256;
            int cc = j >> 6, pp = j & 63;
            featS[cc][pp] = feat[fbase + (size_t)(c0 + cc) * HW + pp];
        }
#pragma unroll
        for (int k = 0; k < 4; k++) {
            int j = t + k * 256;
            WS[j >> 5][j & 31] = Wp[(size_t)(c0 + (j >> 5)) * 32 + (j & 31)];
        }
        __syncthreads();
#pragma unroll
        for (int cc = 0; cc < 32; cc++) {
            float fv = featS[cc][px];
#pragma unroll
            for (int j = 0; j < 8; j++)
                acc[j] = fmaf(fv, WS[cc][grp * 8 + j], acc[j]);
        }
    }
    float* o = g_pfeat + offs[l] + (size_t)(pixbase + px) * 32 + grp * 8;
    *(float4*)o = make_float4(acc[0], acc[1], acc[2], acc[3]);
    *(float4*)(o + 4) = make_float4(acc[4], acc[5], acc[6], acc[7]);
}

// ---------------- copy x0 token slice to output ----------------
__global__ void copy_x0_kernel(const float* __restrict__ x, float* __restrict__ out) {
    int i = blockIdx.x * blockDim.x + threadIdx.x;
    int b = i >> 16;
    int r = i & 65535;
    const float4* xi = (const float4*)x;
    float4* oo = (float4*)out;
    size_t off = (size_t)b * (6 * 65536) + r;
    oo[off] = xi[off];
}

// ---------------- fused token kernel: 8 tokens per block, 256 threads ----------------
__global__ __launch_bounds__(256) void token_fused(
    const float* __restrict__ x, const float* __restrict__ ref,
    const float* __restrict__ n1g, const float* __restrict__ n1b,
    const float* __restrict__ awW, const float* __restrict__ awb,
    const float* __restrict__ soW, const float* __restrict__ sob,
    const float* __restrict__ n2g, const float* __restrict__ n2b,
    float* __restrict__ out) {
    __shared__ __align__(16) float hT_sh[256][12]; // 12KB : hT[k][tok] (8 used, pad 12)
    __shared__ float logit_sh[8][96];              // 3KB
    __shared__ float aw_sh[8][32];                 // 1KB
    __shared__ int   tap_sh[8][32][4];             // 4KB
    __shared__ float wgt_sh[8][32][4];             // 4KB
    __shared__ float o_sh[8][256];                 // 8KB

    int t = threadIdx.x, lane = t & 31, w = t >> 5;
    int m0 = blockIdx.x * 8;
    int b = m0 / 5120;
    int lp = m0 - b * 5120;
    int l = lp >> 10;
    int p0 = lp & 1023;
    size_t base_q = ((size_t)(b * 6 + l + 1) * 1024 + p0) * 256;
    size_t base_0 = ((size_t)(b * 6) * 1024 + p0) * 256;

    const int lvlW_[5] = {128, 64, 32, 16, 16};
    const int lvlOff_[5] = {0, 2097152, 2621440, 2752512, 2785280};
    const int W = lvlW_[l];
    const float* lvlbase = g_pfeat + lvlOff_[l] + (size_t)b * W * W * 32;

    // ---- P1: LN1, warp w handles token w; write TRANSPOSED h ----
    {
        size_t xq_off = base_q + (size_t)w * 256;
        size_t x0_off = base_0 + (size_t)w * 256;
        float sv[8];
        float s = 0.0f;
#pragma unroll
        for (int i = 0; i < 8; i++) {
            int c = lane + 32 * i;
            sv[i] = x[xq_off + c] + x[x0_off + c];
            s += sv[i];
        }
#pragma unroll
        for (int o = 16; o > 0; o >>= 1) s += __shfl_xor_sync(0xffffffffu, s, o);
        float mean = s * (1.0f / 256.0f);
        float v = 0.0f;
#pragma unroll
        for (int i = 0; i < 8; i++) { float d = sv[i] - mean; v += d * d; }
#pragma unroll
        for (int o = 16; o > 0; o >>= 1) v += __shfl_xor_sync(0xffffffffu, v, o);
        float rstd = rsqrtf(v * (1.0f / 256.0f) + 1e-5f);
#pragma unroll
        for (int i = 0; i < 8; i++) {
            int c = lane + 32 * i;
            hT_sh[c][w] = (sv[i] - mean) * rstd * n1g[c] + n1b[c];
        }
    }
    __syncthreads();

    // ---- P2: head logits. thread j = output col, all 8 tokens in registers ----
    // per k: ONE 4B weight load (L1-hot, warp-coalesced) + 2 broadcast LDS.128 -> 8 FMA
    if (t < 96) {
        int j = t;
        const float* wcol;
        int stride;
        float bias;
        if (j < 32) { wcol = awW + j; stride = 32; bias = awb[j]; }
        else        { wcol = soW + (j - 32); stride = 64; bias = sob[j - 32]; }
        float acc0 = bias, acc1 = bias, acc2 = bias, acc3 = bias;
        float acc4 = bias, acc5 = bias, acc6 = bias, acc7 = bias;
#pragma unroll 4
        for (int k = 0; k < 256; k++) {
            float wv = __ldg(wcol + (size_t)k * stride);
            float4 hA = *(const float4*)&hT_sh[k][0];
            float4 hB = *(const float4*)&hT_sh[k][4];
            acc0 = fmaf(hA.x, wv, acc0);
            acc1 = fmaf(hA.y, wv, acc1);
            acc2 = fmaf(hA.z, wv, acc2);
            acc3 = fmaf(hA.w, wv, acc3);
            acc4 = fmaf(hB.x, wv, acc4);
            acc5 = fmaf(hB.y, wv, acc5);
            acc6 = fmaf(hB.z, wv, acc6);
            acc7 = fmaf(hB.w, wv, acc7);
        }
        logit_sh[0][j] = acc0; logit_sh[1][j] = acc1;
        logit_sh[2][j] = acc2; logit_sh[3][j] = acc3;
        logit_sh[4][j] = acc4; logit_sh[5][j] = acc5;
        logit_sh[6][j] = acc6; logit_sh[7][j] = acc7;
    }
    __syncthreads();

    // ---- P3a: softmax over NS=4 per head (64 threads) ----
    if (t < 64) {
        int tok = t >> 3, hd = t & 7;
        float v0 = logit_sh[tok][hd * 4 + 0], v1 = logit_sh[tok][hd * 4 + 1];
        float v2 = logit_sh[tok][hd * 4 + 2], v3 = logit_sh[tok][hd * 4 + 3];
        float mx = fmaxf(fmaxf(v0, v1), fmaxf(v2, v3));
        float e0 = expf(v0 - mx), e1 = expf(v1 - mx), e2 = expf(v2 - mx), e3 = expf(v3 - mx);
        float inv = 1.0f / (e0 + e1 + e2 + e3);
        aw_sh[tok][hd * 4 + 0] = e0 * inv;
        aw_sh[tok][hd * 4 + 1] = e1 * inv;
        aw_sh[tok][hd * 4 + 2] = e2 * inv;
        aw_sh[tok][hd * 4 + 3] = e3 * inv;
    }
    __syncthreads();

    // ---- P3b: per (tok, q) compute taps + combined weights ----
    {
        int tok = t >> 5, q = lane;
        float rx = ref[((size_t)b * 1024 + p0 + tok) * 2 + 0];
        float ry = ref[((size_t)b * 1024 + p0 + tok) * 2 + 1];
        float px_ = tanhf(logit_sh[tok][32 + 2 * q + 0]) + rx;
        float py_ = tanhf(logit_sh[tok][32 + 2 * q + 1]) + ry;
        float fw = (float)(W - 1);
        float gx = fminf(fmaxf((px_ + 1.0f) * 0.5f * fw, 0.0f), fw);
        float gy = fminf(fmaxf((py_ + 1.0f) * 0.5f * fw, 0.0f), fw);
        float x0f = floorf(gx), y0f = floorf(gy);
        float wx = gx - x0f, wy = gy - y0f;
        int x0i = (int)x0f, y0i = (int)y0f;
        int x1i = min(x0i + 1, W - 1), y1i = min(y0i + 1, W - 1);
        tap_sh[tok][q][0] = (y0i * W + x0i) * 32;
        tap_sh[tok][q][1] = (y0i * W + x1i) * 32;
        tap_sh[tok][q][2] = (y1i * W + x0i) * 32;
        tap_sh[tok][q][3] = (y1i * W + x1i) * 32;
        float a = aw_sh[tok][q];
        wgt_sh[tok][q][0] = a * (1.0f - wx) * (1.0f - wy);
        wgt_sh[tok][q][1] = a * wx * (1.0f - wy);
        wgt_sh[tok][q][2] = a * (1.0f - wx) * wy;
        wgt_sh[tok][q][3] = a * wx * wy;
    }
    __syncthreads();

    // ---- P4: coalesced gather + head accumulate ----
#pragma unroll
    for (int iter = 0; iter < 2; iter++) {
        int slot = t + 256 * iter;           // 0..511
        int tok = slot >> 6;
        int head = (slot >> 3) & 7;
        int cg = (slot & 7) * 4;
        float ax = 0.0f, ay = 0.0f, az = 0.0f, aw4 = 0.0f;
#pragma unroll
        for (int s = 0; s < 4; s++) {
            int q = head * 4 + s;
            const int* tp = tap_sh[tok][q];
            const float* wt = wgt_sh[tok][q];
#pragma unroll
            for (int tap = 0; tap < 4; tap++) {
                float4 f = *(const float4*)(lvlbase + tp[tap] + cg);
                float wv = wt[tap];
                ax = fmaf(wv, f.x, ax);
                ay = fmaf(wv, f.y, ay);
                az = fmaf(wv, f.z, az);
                aw4 = fmaf(wv, f.w, aw4);
            }
        }
        *(float4*)&o_sh[tok][head * 32 + cg] = make_float4(ax, ay, az, aw4);
    }
    __syncthreads();

    // ---- P5: residual + LN2 -> bf16 h2 (warp w = token w) ----
    {
        size_t xq_off = base_q + (size_t)w * 256;
        float o8[8];
        float s = 0.0f;
#pragma unroll
        for (int i = 0; i < 8; i++) {
            int c = lane + 32 * i;
            float xq2 = x[xq_off + c] + o_sh[w][c];
            out[xq_off + c] = xq2;
            o8[i] = xq2;
            s += xq2;
        }
#pragma unroll
        for (int o = 16; o > 0; o >>= 1) s += __shfl_xor_sync(0xffffffffu, s, o);
        float mean = s * (1.0f / 256.0f);
        float v = 0.0f;
#pragma unroll
        for (int i = 0; i < 8; i++) { float d = o8[i] - mean; v += d * d; }
#pragma unroll
        for (int o = 16; o > 0; o >>= 1) v += __shfl_xor_sync(0xffffffffu, v, o);
        float rstd = rsqrtf(v * (1.0f / 256.0f) + 1e-5f);
#pragma unroll
        for (int i = 0; i < 8; i++) {
            int c = lane + 32 * i;
            g_h2b[(size_t)(m0 + w) * 256 + c] =
                __float2bfloat16((o8[i] - mean) * rstd * n2g[c] + n2b[c]);
        }
    }
}

// ---------------- bf16 tensor-core GEMM (m16n8k16, fp32 accumulate) ----------------
template <int K, int NDIM, int EPI>
__global__ __launch_bounds__(256, 2) void mma_gemm(const float* __restrict__ bias,
                                                   float* __restrict__ out) {
    const unsigned* A = (EPI == 0) ? (const unsigned*)g_h2b : (const unsigned*)g_mlpb;
    const unsigned* Bpk = (EPI == 0) ? g_w1 : g_w2;
    const int KW = K / 2;

    __shared__ unsigned As[2][128][12];
    __shared__ unsigned Bs[2][8][136];

    int tid = threadIdx.x;
    int m0 = blockIdx.y * 128, n0 = blockIdx.x * 128;

    int aRow = tid >> 1, aColP = (tid & 1) * 4;
    int bR = tid >> 5;
    int bC = (tid & 31) * 4;
    const unsigned* Ap = A + (size_t)(m0 + aRow) * KW + aColP;
    const unsigned* Bp = Bpk + (size_t)bR * NDIM + n0 + bC;

    int lane = tid & 31, wid = tid >> 5;
    int wm = wid & 3, wn = wid >> 2;
    int gid = lane >> 2, tig = lane & 3;

    float acc[2][8][4];
#pragma unroll
    for (int mt = 0; mt < 2; mt++)
#pragma unroll
        for (int nt = 0; nt < 8; nt++)
#pragma unroll
            for (int r = 0; r < 4; r++) acc[mt][nt][r] = 0.0f;

    uint4 av, bv;
    const int NK = K / 16;

    av = *(const uint4*)Ap;
    bv = *(const uint4*)Bp;
    *(uint4*)&As[0][aRow][aColP] = av;
    *(uint4*)&Bs[0][bR][bC] = bv;
    __syncthreads();

    for (int ks = 0; ks < NK; ks++) {
        int buf = ks & 1;
        if (ks + 1 < NK) {
            av = *(const uint4*)(Ap + (ks + 1) * 8);
            bv = *(const uint4*)(Bp + (size_t)(ks + 1) * 8 * NDIM);
        }
        {
            unsigned af[2][4];
#pragma unroll
            for (int mt = 0; mt < 2; mt++) {
                int r = wm * 32 + mt * 16 + gid;
                af[mt][0] = As[buf][r][tig];
                af[mt][1] = As[buf][r + 8][tig];
                af[mt][2] = As[buf][r][tig + 4];
                af[mt][3] = As[buf][r + 8][tig + 4];
            }
#pragma unroll
            for (int nt = 0; nt < 8; nt++) {
                int cb = wn * 64 + nt * 8 + gid;
                unsigned bf0 = Bs[buf][tig][cb];
                unsigned bf1 = Bs[buf][tig + 4][cb];
#pragma unroll
                for (int mt = 0; mt < 2; mt++) {
                    asm volatile(
                        "mma.sync.aligned.m16n8k16.row.col.f32.bf16.bf16.f32 "
                        "{%0,%1,%2,%3},{%4,%5,%6,%7},{%8,%9},{%0,%1,%2,%3};"
                        : "+f"(acc[mt][nt][0]), "+f"(acc[mt][nt][1]),
                          "+f"(acc[mt][nt][2]), "+f"(acc[mt][nt][3])
                        : "r"(af[mt][0]), "r"(af[mt][1]), "r"(af[mt][2]), "r"(af[mt][3]),
                          "r"(bf0), "r"(bf1));
                }
            }
        }
        if (ks + 1 < NK) {
            int nb = (ks + 1) & 1;
            *(uint4*)&As[nb][aRow][aColP] = av;
            *(uint4*)&Bs[nb][bR][bC] = bv;
        }
        __syncthreads();
    }

#pragma unroll
    for (int mt = 0; mt < 2; mt++) {
#pragma unroll
        for (int nt = 0; nt < 8; nt++) {
            int r0 = m0 + wm * 32 + mt * 16 + gid;
            int c = n0 + wn * 64 + nt * 8 + 2 * tig;
            float bv0 = __ldg(bias + c), bv1 = __ldg(bias + c + 1);
            if (EPI == 0) {
                float v0 = acc[mt][nt][0] + bv0, v1 = acc[mt][nt][1] + bv1;
                float v2 = acc[mt][nt][2] + bv0, v3 = acc[mt][nt][3] + bv1;
                unsigned* gm = (unsigned*)g_mlpb;
                gm[((size_t)r0 * 512 + c) >> 1] = pack_bf2(v0 * normcdff(v0), v1 * normcdff(v1));
                gm[((size_t)(r0 + 8) * 512 + c) >> 1] = pack_bf2(v2 * normcdff(v2), v3 * normcdff(v3));
            } else {
#pragma unroll
                for (int half = 0; half < 2; half++) {
                    int row = r0 + half * 8;
                    int bb = row / 5120;
                    int lpp = row - bb * 5120;
                    int ll = lpp >> 10;
                    int pp = lpp & 1023;
                    float* orow = out + ((size_t)(bb * 6 + ll + 1) * 1024 + pp) * 256 + c;
                    float2 cur = *(float2*)orow;
                    cur.x += acc[mt][nt][half * 2 + 0] + bv0;
                    cur.y += acc[mt][nt][half * 2 + 1] + bv1;
                    *(float2*)orow = cur;
                }
            }
        }
    }
}

// ---------------- launch ----------------
extern "C" void kernel_launch(void* const* d_in, const int* in_sizes, int n_in,
                              void* d_out, int out_size) {
    const float* x    = (const float*)d_in[0];
    const float* ref  = (const float*)d_in[1];
    const float* n1g = (const float*)d_in[7];
    const float* n1b = (const float*)d_in[8];
    const float* awW = (const float*)d_in[9];
    const float* awb = (const float*)d_in[10];
    const float* soW = (const float*)d_in[11];
    const float* sob = (const float*)d_in[12];
    const float* n2g  = (const float*)d_in[23];
    const float* n2b  = (const float*)d_in[24];
    const float* fc1W = (const float*)d_in[25];
    const float* fc1b = (const float*)d_in[26];
    const float* fc2W = (const float*)d_in[27];
    const float* fc2b = (const float*)d_in[28];
    float* out = (float*)d_out;

    ProjParams P;
    for (int lvl = 0; lvl < 5; lvl++) {
        P.feat[lvl] = (const float*)d_in[2 + lvl];
        P.W[lvl]    = (const float*)d_in[13 + 2 * lvl];
        P.bias[lvl] = (const float*)d_in[14 + 2 * lvl];
    }

    convert_w<<<512, 256>>>(fc1W, fc2W);
    proj_all<<<1376, 256>>>(P);
    copy_x0_kernel<<<1024, 256>>>(x, out);
    token_fused<<<2560, 256>>>(x, ref, n1g, n1b, awW, awb, soW, sob, n2g, n2b, out);
    mma_gemm<256, 512, 0><<<dim3(4, 160), 256>>>(fc1b, out);
    mma_gemm<512, 256, 1><<<dim3(2, 160), 256>>>(fc2b, out);
}

// round 8
// speedup vs baseline: 3.0156x; 1.0852x over previous
#include <cuda_runtime.h>
#include <cuda_bf16.h>
#include <math.h>

// ---------------- scratch (static device globals; no allocation) ----------------
static __device__ __align__(16) float g_pfeat[2818048];
static __device__ __align__(16) __nv_bfloat16 g_h2b[20480 * 256];
static __device__ __align__(16) __nv_bfloat16 g_mlpb[20480 * 512];
static __device__ __align__(16) unsigned g_w1[128 * 512];   // fc1_W packed (k-pair, col)
static __device__ __align__(16) unsigned g_w2[256 * 256];   // fc2_W packed (k-pair, col)

__device__ __forceinline__ unsigned pack_bf2(float lo, float hi) {
    __nv_bfloat162 h = __floats2bfloat162_rn(lo, hi);
    return *(unsigned*)&h;
}

// ---------------- pre-pack MLP weights to bf16 (k-pair interleaved) ----------------
__global__ void convert_w(const float* __restrict__ fc1W, const float* __restrict__ fc2W) {
    int i = blockIdx.x * blockDim.x + threadIdx.x;    // 0..131071
    if (i < 65536) {
        int kp = i >> 9, n = i & 511;                 // fc1: K=256,N=512
        g_w1[i] = pack_bf2(fc1W[(2 * kp) * 512 + n], fc1W[(2 * kp + 1) * 512 + n]);
    } else {
        int j = i - 65536;
        int kp = j >> 8, n = j & 255;                 // fc2: K=512,N=256
        g_w2[j] = pack_bf2(fc2W[(2 * kp) * 256 + n], fc2W[(2 * kp + 1) * 256 + n]);
    }
}

// ---------------- merged feature projection: one launch, all 5 levels ----------------
struct ProjParams {
    const float* feat[5];
    const float* W[5];
    const float* bias[5];
};

__global__ __launch_bounds__(256) void proj_all(ProjParams P) {
    const int starts[6] = {0, 1024, 1280, 1344, 1360, 1376};
    const int Cs[5]   = {64, 128, 256, 512, 256};
    const int HWs[5]  = {16384, 4096, 1024, 256, 256};
    const int offs[5] = {0, 2097152, 2621440, 2752512, 2785280};

    __shared__ float featS[32][64];
    __shared__ float WS[32][32];

    int blk = blockIdx.x;
    int l = 0;
#pragma unroll
    for (int i = 0; i < 4; i++) if (blk >= starts[l + 1]) l++;
    int tile = blk - starts[l];
    int C = Cs[l], HW = HWs[l];
    int pixbase = tile * 64;
    int b = pixbase / HW;
    int idx0 = pixbase - b * HW;

    const float* feat = P.feat[l];
    const float* Wp = P.W[l];
    const float* bp = P.bias[l];

    int t = threadIdx.x;
    int px = t & 63, grp = t >> 6;

    float acc[8];
#pragma unroll
    for (int j = 0; j < 8; j++) acc[j] = bp[grp * 8 + j];

    size_t fbase = ((size_t)b * C) * HW + idx0;

    for (int c0 = 0; c0 < C; c0 += 32) {
        __syncthreads();
#pragma unroll
        for (int k = 0; k < 8; k++) {
            int j = t + k * 256;
            int cc = j >> 6, pp = j & 63;
            featS[cc][pp] = feat[fbase + (size_t)(c0 + cc) * HW + pp];
        }
#pragma unroll
        for (int k = 0; k < 4; k++) {
            int j = t + k * 256;
            WS[j >> 5][j & 31] = Wp[(size_t)(c0 + (j >> 5)) * 32 + (j & 31)];
        }
        __syncthreads();
#pragma unroll
        for (int cc = 0; cc < 32; cc++) {
            float fv = featS[cc][px];
#pragma unroll
            for (int j = 0; j < 8; j++)
                acc[j] = fmaf(fv, WS[cc][grp * 8 + j], acc[j]);
        }
    }
    float* o = g_pfeat + offs[l] + (size_t)(pixbase + px) * 32 + grp * 8;
    *(float4*)o = make_float4(acc[0], acc[1], acc[2], acc[3]);
    *(float4*)(o + 4) = make_float4(acc[4], acc[5], acc[6], acc[7]);
}

// ---------------- copy x0 token slice to output ----------------
__global__ void copy_x0_kernel(const float* __restrict__ x, float* __restrict__ out) {
    int i = blockIdx.x * blockDim.x + threadIdx.x;
    int b = i >> 16;
    int r = i & 65535;
    const float4* xi = (const float4*)x;
    float4* oo = (float4*)out;
    size_t off = (size_t)b * (6 * 65536) + r;
    oo[off] = xi[off];
}

// ---------------- fused token kernel: 8 tokens per block, 256 threads ----------------
__global__ __launch_bounds__(256) void token_fused(
    const float* __restrict__ x, const float* __restrict__ ref,
    const float* __restrict__ n1g, const float* __restrict__ n1b,
    const float* __restrict__ awW, const float* __restrict__ awb,
    const float* __restrict__ soW, const float* __restrict__ sob,
    const float* __restrict__ n2g, const float* __restrict__ n2b,
    float* __restrict__ out) {
    __shared__ __align__(16) float hT_sh[256][12]; // 12KB : hT[k][tok]
    __shared__ float logit_sh[8][96];              // 3KB : k-half 0 (+bias)
    __shared__ float logit2_sh[8][96];             // 3KB : k-half 1
    __shared__ float aw_sh[8][32];                 // 1KB
    __shared__ __align__(16) int   tap_sh[8][32][4];   // 4KB
    __shared__ __align__(16) float wgt_sh[8][32][4];   // 4KB
    __shared__ float o_sh[8][256];                 // 8KB

    int t = threadIdx.x, lane = t & 31, w = t >> 5;
    int m0 = blockIdx.x * 8;
    int b = m0 / 5120;
    int lp = m0 - b * 5120;
    int l = lp >> 10;
    int p0 = lp & 1023;
    size_t base_q = ((size_t)(b * 6 + l + 1) * 1024 + p0) * 256;
    size_t base_0 = ((size_t)(b * 6) * 1024 + p0) * 256;

    const int lvlW_[5] = {128, 64, 32, 16, 16};
    const int lvlOff_[5] = {0, 2097152, 2621440, 2752512, 2785280};
    const int W = lvlW_[l];
    const float* lvlbase = g_pfeat + lvlOff_[l] + (size_t)b * W * W * 32;

    // ---- P1: LN1, warp w handles token w; write TRANSPOSED h ----
    {
        size_t xq_off = base_q + (size_t)w * 256;
        size_t x0_off = base_0 + (size_t)w * 256;
        float sv[8];
        float s = 0.0f;
#pragma unroll
        for (int i = 0; i < 8; i++) {
            int c = lane + 32 * i;
            sv[i] = x[xq_off + c] + x[x0_off + c];
            s += sv[i];
        }
#pragma unroll
        for (int o = 16; o > 0; o >>= 1) s += __shfl_xor_sync(0xffffffffu, s, o);
        float mean = s * (1.0f / 256.0f);
        float v = 0.0f;
#pragma unroll
        for (int i = 0; i < 8; i++) { float d = sv[i] - mean; v += d * d; }
#pragma unroll
        for (int o = 16; o > 0; o >>= 1) v += __shfl_xor_sync(0xffffffffu, v, o);
        float rstd = rsqrtf(v * (1.0f / 256.0f) + 1e-5f);
#pragma unroll
        for (int i = 0; i < 8; i++) {
            int c = lane + 32 * i;
            hT_sh[c][w] = (sv[i] - mean) * rstd * n1g[c] + n1b[c];
        }
    }
    __syncthreads();

    // ---- P2: head logits, k-split across 2 halves (192 threads, 6 warps) ----
    // thread = (col j, half). per k: ONE 4B weight load + 2 broadcast LDS.128 -> 8 FMA
    if (t < 192) {
        int half = t >= 96;
        int j = t - 96 * half;
        int k0 = half * 128;
        const float* wcol;
        int stride;
        float bias = 0.0f;
        if (j < 32) { wcol = awW + j; stride = 32; if (!half) bias = awb[j]; }
        else        { wcol = soW + (j - 32); stride = 64; if (!half) bias = sob[j - 32]; }
        wcol += (size_t)k0 * stride;
        float acc0 = bias, acc1 = bias, acc2 = bias, acc3 = bias;
        float acc4 = bias, acc5 = bias, acc6 = bias, acc7 = bias;
#pragma unroll 8
        for (int k = 0; k < 128; k++) {
            float wv = __ldg(wcol + (size_t)k * stride);
            float4 hA = *(const float4*)&hT_sh[k0 + k][0];
            float4 hB = *(const float4*)&hT_sh[k0 + k][4];
            acc0 = fmaf(hA.x, wv, acc0);
            acc1 = fmaf(hA.y, wv, acc1);
            acc2 = fmaf(hA.z, wv, acc2);
            acc3 = fmaf(hA.w, wv, acc3);
            acc4 = fmaf(hB.x, wv, acc4);
            acc5 = fmaf(hB.y, wv, acc5);
            acc6 = fmaf(hB.z, wv, acc6);
            acc7 = fmaf(hB.w, wv, acc7);
        }
        float (*dst)[96] = half ? logit2_sh : logit_sh;
        dst[0][j] = acc0; dst[1][j] = acc1;
        dst[2][j] = acc2; dst[3][j] = acc3;
        dst[4][j] = acc4; dst[5][j] = acc5;
        dst[6][j] = acc6; dst[7][j] = acc7;
    }
    __syncthreads();

    // ---- P3a: softmax over NS=4 per head (64 threads) ----
    if (t < 64) {
        int tok = t >> 3, hd = t & 7;
        float v0 = logit_sh[tok][hd * 4 + 0] + logit2_sh[tok][hd * 4 + 0];
        float v1 = logit_sh[tok][hd * 4 + 1] + logit2_sh[tok][hd * 4 + 1];
        float v2 = logit_sh[tok][hd * 4 + 2] + logit2_sh[tok][hd * 4 + 2];
        float v3 = logit_sh[tok][hd * 4 + 3] + logit2_sh[tok][hd * 4 + 3];
        float mx = fmaxf(fmaxf(v0, v1), fmaxf(v2, v3));
        float e0 = expf(v0 - mx), e1 = expf(v1 - mx), e2 = expf(v2 - mx), e3 = expf(v3 - mx);
        float inv = 1.0f / (e0 + e1 + e2 + e3);
        aw_sh[tok][hd * 4 + 0] = e0 * inv;
        aw_sh[tok][hd * 4 + 1] = e1 * inv;
        aw_sh[tok][hd * 4 + 2] = e2 * inv;
        aw_sh[tok][hd * 4 + 3] = e3 * inv;
    }
    __syncthreads();

    // ---- P3b: per (tok, q) compute taps + combined weights ----
    {
        int tok = t >> 5, q = lane;
        float rx = ref[((size_t)b * 1024 + p0 + tok) * 2 + 0];
        float ry = ref[((size_t)b * 1024 + p0 + tok) * 2 + 1];
        float lx = logit_sh[tok][32 + 2 * q + 0] + logit2_sh[tok][32 + 2 * q + 0];
        float ly = logit_sh[tok][32 + 2 * q + 1] + logit2_sh[tok][32 + 2 * q + 1];
        float px_ = tanhf(lx) + rx;
        float py_ = tanhf(ly) + ry;
        float fw = (float)(W - 1);
        float gx = fminf(fmaxf((px_ + 1.0f) * 0.5f * fw, 0.0f), fw);
        float gy = fminf(fmaxf((py_ + 1.0f) * 0.5f * fw, 0.0f), fw);
        float x0f = floorf(gx), y0f = floorf(gy);
        float wx = gx - x0f, wy = gy - y0f;
        int x0i = (int)x0f, y0i = (int)y0f;
        int x1i = min(x0i + 1, W - 1), y1i = min(y0i + 1, W - 1);
        *(int4*)tap_sh[tok][q] = make_int4((y0i * W + x0i) * 32, (y0i * W + x1i) * 32,
                                           (y1i * W + x0i) * 32, (y1i * W + x1i) * 32);
        float a = aw_sh[tok][q];
        *(float4*)wgt_sh[tok][q] = make_float4(a * (1.0f - wx) * (1.0f - wy),
                                               a * wx * (1.0f - wy),
                                               a * (1.0f - wx) * wy,
                                               a * wx * wy);
    }
    __syncthreads();

    // ---- P4: coalesced gather + head accumulate ----
#pragma unroll
    for (int iter = 0; iter < 2; iter++) {
        int slot = t + 256 * iter;           // 0..511
        int tok = slot >> 6;
        int head = (slot >> 3) & 7;
        int cg = (slot & 7) * 4;
        float ax = 0.0f, ay = 0.0f, az = 0.0f, aw4 = 0.0f;
#pragma unroll
        for (int s = 0; s < 4; s++) {
            int q = head * 4 + s;
            int4 tp = *(const int4*)tap_sh[tok][q];
            float4 wt = *(const float4*)wgt_sh[tok][q];
            float4 f0 = *(const float4*)(lvlbase + tp.x + cg);
            float4 f1 = *(const float4*)(lvlbase + tp.y + cg);
            float4 f2 = *(const float4*)(lvlbase + tp.z + cg);
            float4 f3 = *(const float4*)(lvlbase + tp.w + cg);
            ax = fmaf(wt.x, f0.x, fmaf(wt.y, f1.x, fmaf(wt.z, f2.x, fmaf(wt.w, f3.x, ax))));
            ay = fmaf(wt.x, f0.y, fmaf(wt.y, f1.y, fmaf(wt.z, f2.y, fmaf(wt.w, f3.y, ay))));
            az = fmaf(wt.x, f0.z, fmaf(wt.y, f1.z, fmaf(wt.z, f2.z, fmaf(wt.w, f3.z, az))));
            aw4 = fmaf(wt.x, f0.w, fmaf(wt.y, f1.w, fmaf(wt.z, f2.w, fmaf(wt.w, f3.w, aw4))));
        }
        *(float4*)&o_sh[tok][head * 32 + cg] = make_float4(ax, ay, az, aw4);
    }
    __syncthreads();

    // ---- P5: residual + LN2 -> bf16 h2 (warp w = token w) ----
    {
        size_t xq_off = base_q + (size_t)w * 256;
        float o8[8];
        float s = 0.0f;
#pragma unroll
        for (int i = 0; i < 8; i++) {
            int c = lane + 32 * i;
            float xq2 = x[xq_off + c] + o_sh[w][c];
            out[xq_off + c] = xq2;
            o8[i] = xq2;
            s += xq2;
        }
#pragma unroll
        for (int o = 16; o > 0; o >>= 1) s += __shfl_xor_sync(0xffffffffu, s, o);
        float mean = s * (1.0f / 256.0f);
        float v = 0.0f;
#pragma unroll
        for (int i = 0; i < 8; i++) { float d = o8[i] - mean; v += d * d; }
#pragma unroll
        for (int o = 16; o > 0; o >>= 1) v += __shfl_xor_sync(0xffffffffu, v, o);
        float rstd = rsqrtf(v * (1.0f / 256.0f) + 1e-5f);
#pragma unroll
        for (int i = 0; i < 8; i++) {
            int c = lane + 32 * i;
            g_h2b[(size_t)(m0 + w) * 256 + c] =
                __float2bfloat16((o8[i] - mean) * rstd * n2g[c] + n2b[c]);
        }
    }
}

// ---------------- bf16 tensor-core GEMM (m16n8k16, fp32 accumulate) ----------------
template <int K, int NDIM, int EPI>
__global__ __launch_bounds__(256, 2) void mma_gemm(const float* __restrict__ bias,
                                                   float* __restrict__ out) {
    const unsigned* A = (EPI == 0) ? (const unsigned*)g_h2b : (const unsigned*)g_mlpb;
    const unsigned* Bpk = (EPI == 0) ? g_w1 : g_w2;
    const int KW = K / 2;

    __shared__ unsigned As[2][128][12];
    __shared__ unsigned Bs[2][8][136];

    int tid = threadIdx.x;
    int m0 = blockIdx.y * 128, n0 = blockIdx.x * 128;

    int aRow = tid >> 1, aColP = (tid & 1) * 4;
    int bR = tid >> 5;
    int bC = (tid & 31) * 4;
    const unsigned* Ap = A + (size_t)(m0 + aRow) * KW + aColP;
    const unsigned* Bp = Bpk + (size_t)bR * NDIM + n0 + bC;

    int lane = tid & 31, wid = tid >> 5;
    int wm = wid & 3, wn = wid >> 2;
    int gid = lane >> 2, tig = lane & 3;

    float acc[2][8][4];
#pragma unroll
    for (int mt = 0; mt < 2; mt++)
#pragma unroll
        for (int nt = 0; nt < 8; nt++)
#pragma unroll
            for (int r = 0; r < 4; r++) acc[mt][nt][r] = 0.0f;

    uint4 av, bv;
    const int NK = K / 16;

    av = *(const uint4*)Ap;
    bv = *(const uint4*)Bp;
    *(uint4*)&As[0][aRow][aColP] = av;
    *(uint4*)&Bs[0][bR][bC] = bv;
    __syncthreads();

    for (int ks = 0; ks < NK; ks++) {
        int buf = ks & 1;
        if (ks + 1 < NK) {
            av = *(const uint4*)(Ap + (ks + 1) * 8);
            bv = *(const uint4*)(Bp + (size_t)(ks + 1) * 8 * NDIM);
        }
        {
            unsigned af[2][4];
#pragma unroll
            for (int mt = 0; mt < 2; mt++) {
                int r = wm * 32 + mt * 16 + gid;
                af[mt][0] = As[buf][r][tig];
                af[mt][1] = As[buf][r + 8][tig];
                af[mt][2] = As[buf][r][tig + 4];
                af[mt][3] = As[buf][r + 8][tig + 4];
            }
#pragma unroll
            for (int nt = 0; nt < 8; nt++) {
                int cb = wn * 64 + nt * 8 + gid;
                unsigned bf0 = Bs[buf][tig][cb];
                unsigned bf1 = Bs[buf][tig + 4][cb];
#pragma unroll
                for (int mt = 0; mt < 2; mt++) {
                    asm volatile(
                        "mma.sync.aligned.m16n8k16.row.col.f32.bf16.bf16.f32 "
                        "{%0,%1,%2,%3},{%4,%5,%6,%7},{%8,%9},{%0,%1,%2,%3};"
                        : "+f"(acc[mt][nt][0]), "+f"(acc[mt][nt][1]),
                          "+f"(acc[mt][nt][2]), "+f"(acc[mt][nt][3])
                        : "r"(af[mt][0]), "r"(af[mt][1]), "r"(af[mt][2]), "r"(af[mt][3]),
                          "r"(bf0), "r"(bf1));
                }
            }
        }
        if (ks + 1 < NK) {
            int nb = (ks + 1) & 1;
            *(uint4*)&As[nb][aRow][aColP] = av;
            *(uint4*)&Bs[nb][bR][bC] = bv;
        }
        __syncthreads();
    }

#pragma unroll
    for (int mt = 0; mt < 2; mt++) {
#pragma unroll
        for (int nt = 0; nt < 8; nt++) {
            int r0 = m0 + wm * 32 + mt * 16 + gid;
            int c = n0 + wn * 64 + nt * 8 + 2 * tig;
            float bv0 = __ldg(bias + c), bv1 = __ldg(bias + c + 1);
            if (EPI == 0) {
                float v0 = acc[mt][nt][0] + bv0, v1 = acc[mt][nt][1] + bv1;
                float v2 = acc[mt][nt][2] + bv0, v3 = acc[mt][nt][3] + bv1;
                unsigned* gm = (unsigned*)g_mlpb;
                gm[((size_t)r0 * 512 + c) >> 1] = pack_bf2(v0 * normcdff(v0), v1 * normcdff(v1));
                gm[((size_t)(r0 + 8) * 512 + c) >> 1] = pack_bf2(v2 * normcdff(v2), v3 * normcdff(v3));
            } else {
#pragma unroll
                for (int half = 0; half < 2; half++) {
                    int row = r0 + half * 8;
                    int bb = row / 5120;
                    int lpp = row - bb * 5120;
                    int ll = lpp >> 10;
                    int pp = lpp & 1023;
                    float* orow = out + ((size_t)(bb * 6 + ll + 1) * 1024 + pp) * 256 + c;
                    float2 cur = *(float2*)orow;
                    cur.x += acc[mt][nt][half * 2 + 0] + bv0;
                    cur.y += acc[mt][nt][half * 2 + 1] + bv1;
                    *(float2*)orow = cur;
                }
            }
        }
    }
}

// ---------------- launch ----------------
extern "C" void kernel_launch(void* const* d_in, const int* in_sizes, int n_in,
                              void* d_out, int out_size) {
    const float* x    = (const float*)d_in[0];
    const float* ref  = (const float*)d_in[1];
    const float* n1g = (const float*)d_in[7];
    const float* n1b = (const float*)d_in[8];
    const float* awW = (const float*)d_in[9];
    const float* awb = (const float*)d_in[10];
    const float* soW = (const float*)d_in[11];
    const float* sob = (const float*)d_in[12];
    const float* n2g  = (const float*)d_in[23];
    const float* n2b  = (const float*)d_in[24];
    const float* fc1W = (const float*)d_in[25];
    const float* fc1b = (const float*)d_in[26];
    const float* fc2W = (const float*)d_in[27];
    const float* fc2b = (const float*)d_in[28];
    float* out = (float*)d_out;

    ProjParams P;
    for (int lvl = 0; lvl < 5; lvl++) {
        P.feat[lvl] = (const float*)d_in[2 + lvl];
        P.W[lvl]    = (const float*)d_in[13 + 2 * lvl];
        P.bias[lvl] = (const float*)d_in[14 + 2 * lvl];
    }

    convert_w<<<512, 256>>>(fc1W, fc2W);
    proj_all<<<1376, 256>>>(P);
    copy_x0_kernel<<<1024, 256>>>(x, out);
    token_fused<<<2560, 256>>>(x, ref, n1g, n1b, awW, awb, soW, sob, n2g, n2b, out);
    mma_gemm<256, 512, 0><<<dim3(4, 160), 256>>>(fc1b, out);
    mma_gemm<512, 256, 1><<<dim3(2, 160), 256>>>(fc2b, out);
}

// round 9
// speedup vs baseline: 3.0397x; 1.0080x over previous
#include <cuda_runtime.h>
#include <cuda_bf16.h>
#include <math.h>

// ---------------- scratch (static device globals; no allocation) ----------------
static __device__ __align__(16) float g_pfeat[2818048];
static __device__ __align__(16) __nv_bfloat16 g_h2b[20480 * 256];
static __device__ __align__(16) __nv_bfloat16 g_mlpb[20480 * 512];
// fragment-ready packed weights: uint4[ks][gg][lane] (see convert_w)
static __device__ __align__(16) unsigned g_w1[128 * 512];   // fc1: 16 ks x 32 gg x 32 lanes
static __device__ __align__(16) unsigned g_w2[256 * 256];   // fc2: 32 ks x 16 gg x 32 lanes

__device__ __forceinline__ unsigned pack_bf2(float lo, float hi) {
    __nv_bfloat162 h = __floats2bfloat162_rn(lo, hi);
    return *(unsigned*)&h;
}

// ---------------- pre-pack MLP weights into mma-fragment order ----------------
// For k-step ks, column-group-pair gg, lane (gid=lane>>2, tig=lane&3):
//   x = {W[ks*16+2tig  ][gg*16+gid],   W[ks*16+2tig+1][gg*16+gid]}
//   y = {W[ks*16+2tig+8][gg*16+gid],   W[ks*16+2tig+9][gg*16+gid]}
//   z,w = same with col+8
__global__ void convert_w(const float* __restrict__ fc1W, const float* __restrict__ fc2W) {
    int i = blockIdx.x * blockDim.x + threadIdx.x;    // 0..32767 uint4s
    bool is2 = i >= 16384;
    int j = is2 ? i - 16384 : i;
    const float* Wsrc = is2 ? fc2W : fc1W;
    int N = is2 ? 256 : 512;
    int GG = N / 16;
    int lane = j & 31;
    int gg = (j >> 5) % GG;
    int ks = (j >> 5) / GG;
    int gid = lane >> 2, tig = lane & 3;
    int col = gg * 16 + gid;
    int k0 = ks * 16 + 2 * tig;
    uint4 u;
    u.x = pack_bf2(Wsrc[(size_t)(k0 + 0) * N + col],     Wsrc[(size_t)(k0 + 1) * N + col]);
    u.y = pack_bf2(Wsrc[(size_t)(k0 + 8) * N + col],     Wsrc[(size_t)(k0 + 9) * N + col]);
    u.z = pack_bf2(Wsrc[(size_t)(k0 + 0) * N + col + 8], Wsrc[(size_t)(k0 + 1) * N + col + 8]);
    u.w = pack_bf2(Wsrc[(size_t)(k0 + 8) * N + col + 8], Wsrc[(size_t)(k0 + 9) * N + col + 8]);
    ((uint4*)(is2 ? (void*)g_w2 : (void*)g_w1))[j] = u;
}

// ---------------- merged feature projection: one launch, all 5 levels ----------------
struct ProjParams {
    const float* feat[5];
    const float* W[5];
    const float* bias[5];
};

__global__ __launch_bounds__(256) void proj_all(ProjParams P) {
    const int starts[6] = {0, 1024, 1280, 1344, 1360, 1376};
    const int Cs[5]   = {64, 128, 256, 512, 256};
    const int HWs[5]  = {16384, 4096, 1024, 256, 256};
    const int offs[5] = {0, 2097152, 2621440, 2752512, 2785280};

    __shared__ float featS[32][64];
    __shared__ float WS[32][32];

    int blk = blockIdx.x;
    int l = 0;
#pragma unroll
    for (int i = 0; i < 4; i++) if (blk >= starts[l + 1]) l++;
    int tile = blk - starts[l];
    int C = Cs[l], HW = HWs[l];
    int pixbase = tile * 64;
    int b = pixbase / HW;
    int idx0 = pixbase - b * HW;

    const float* feat = P.feat[l];
    const float* Wp = P.W[l];
    const float* bp = P.bias[l];

    int t = threadIdx.x;
    int px = t & 63, grp = t >> 6;

    float acc[8];
#pragma unroll
    for (int j = 0; j < 8; j++) acc[j] = bp[grp * 8 + j];

    size_t fbase = ((size_t)b * C) * HW + idx0;

    for (int c0 = 0; c0 < C; c0 += 32) {
        __syncthreads();
#pragma unroll
        for (int k = 0; k < 8; k++) {
            int j = t + k * 256;
            int cc = j >> 6, pp = j & 63;
            featS[cc][pp] = feat[fbase + (size_t)(c0 + cc) * HW + pp];
        }
#pragma unroll
        for (int k = 0; k < 4; k++) {
            int j = t + k * 256;
            WS[j >> 5][j & 31] = Wp[(size_t)(c0 + (j >> 5)) * 32 + (j & 31)];
        }
        __syncthreads();
#pragma unroll
        for (int cc = 0; cc < 32; cc++) {
            float fv = featS[cc][px];
#pragma unroll
            for (int j = 0; j < 8; j++)
                acc[j] = fmaf(fv, WS[cc][grp * 8 + j], acc[j]);
        }
    }
    float* o = g_pfeat + offs[l] + (size_t)(pixbase + px) * 32 + grp * 8;
    *(float4*)o = make_float4(acc[0], acc[1], acc[2], acc[3]);
    *(float4*)(o + 4) = make_float4(acc[4], acc[5], acc[6], acc[7]);
}

// ---------------- copy x0 token slice to output ----------------
__global__ void copy_x0_kernel(const float* __restrict__ x, float* __restrict__ out) {
    int i = blockIdx.x * blockDim.x + threadIdx.x;
    int b = i >> 16;
    int r = i & 65535;
    const float4* xi = (const float4*)x;
    float4* oo = (float4*)out;
    size_t off = (size_t)b * (6 * 65536) + r;
    oo[off] = xi[off];
}

// ---------------- fused token kernel: 8 tokens per block, 256 threads ----------------
__global__ __launch_bounds__(256) void token_fused(
    const float* __restrict__ x, const float* __restrict__ ref,
    const float* __restrict__ n1g, const float* __restrict__ n1b,
    const float* __restrict__ awW, const float* __restrict__ awb,
    const float* __restrict__ soW, const float* __restrict__ sob,
    const float* __restrict__ n2g, const float* __restrict__ n2b,
    float* __restrict__ out) {
    __shared__ __align__(16) float hT_sh[256][12]; // 12KB : hT[k][tok]
    __shared__ float logit_sh[8][96];              // 3KB : k-half 0 (+bias)
    __shared__ float logit2_sh[8][96];             // 3KB : k-half 1
    __shared__ float aw_sh[8][32];                 // 1KB
    __shared__ __align__(16) int   tap_sh[8][32][4];   // 4KB
    __shared__ __align__(16) float wgt_sh[8][32][4];   // 4KB
    __shared__ float o_sh[8][256];                 // 8KB

    int t = threadIdx.x, lane = t & 31, w = t >> 5;
    int m0 = blockIdx.x * 8;
    int b = m0 / 5120;
    int lp = m0 - b * 5120;
    int l = lp >> 10;
    int p0 = lp & 1023;
    size_t base_q = ((size_t)(b * 6 + l + 1) * 1024 + p0) * 256;
    size_t base_0 = ((size_t)(b * 6) * 1024 + p0) * 256;

    const int lvlW_[5] = {128, 64, 32, 16, 16};
    const int lvlOff_[5] = {0, 2097152, 2621440, 2752512, 2785280};
    const int W = lvlW_[l];
    const float* lvlbase = g_pfeat + lvlOff_[l] + (size_t)b * W * W * 32;

    // ---- P1: LN1, warp w handles token w; write TRANSPOSED h ----
    {
        size_t xq_off = base_q + (size_t)w * 256;
        size_t x0_off = base_0 + (size_t)w * 256;
        float sv[8];
        float s = 0.0f;
#pragma unroll
        for (int i = 0; i < 8; i++) {
            int c = lane + 32 * i;
            sv[i] = x[xq_off + c] + x[x0_off + c];
            s += sv[i];
        }
#pragma unroll
        for (int o = 16; o > 0; o >>= 1) s += __shfl_xor_sync(0xffffffffu, s, o);
        float mean = s * (1.0f / 256.0f);
        float v = 0.0f;
#pragma unroll
        for (int i = 0; i < 8; i++) { float d = sv[i] - mean; v += d * d; }
#pragma unroll
        for (int o = 16; o > 0; o >>= 1) v += __shfl_xor_sync(0xffffffffu, v, o);
        float rstd = rsqrtf(v * (1.0f / 256.0f) + 1e-5f);
#pragma unroll
        for (int i = 0; i < 8; i++) {
            int c = lane + 32 * i;
            hT_sh[c][w] = (sv[i] - mean) * rstd * n1g[c] + n1b[c];
        }
    }
    __syncthreads();

    // ---- P2: head logits, k-split across 2 halves (192 threads, 6 warps) ----
    if (t < 192) {
        int half = t >= 96;
        int j = t - 96 * half;
        int k0 = half * 128;
        const float* wcol;
        int stride;
        float bias = 0.0f;
        if (j < 32) { wcol = awW + j; stride = 32; if (!half) bias = awb[j]; }
        else        { wcol = soW + (j - 32); stride = 64; if (!half) bias = sob[j - 32]; }
        wcol += (size_t)k0 * stride;
        float acc0 = bias, acc1 = bias, acc2 = bias, acc3 = bias;
        float acc4 = bias, acc5 = bias, acc6 = bias, acc7 = bias;
#pragma unroll 8
        for (int k = 0; k < 128; k++) {
            float wv = __ldg(wcol + (size_t)k * stride);
            float4 hA = *(const float4*)&hT_sh[k0 + k][0];
            float4 hB = *(const float4*)&hT_sh[k0 + k][4];
            acc0 = fmaf(hA.x, wv, acc0);
            acc1 = fmaf(hA.y, wv, acc1);
            acc2 = fmaf(hA.z, wv, acc2);
            acc3 = fmaf(hA.w, wv, acc3);
            acc4 = fmaf(hB.x, wv, acc4);
            acc5 = fmaf(hB.y, wv, acc5);
            acc6 = fmaf(hB.z, wv, acc6);
            acc7 = fmaf(hB.w, wv, acc7);
        }
        float (*dst)[96] = half ? logit2_sh : logit_sh;
        dst[0][j] = acc0; dst[1][j] = acc1;
        dst[2][j] = acc2; dst[3][j] = acc3;
        dst[4][j] = acc4; dst[5][j] = acc5;
        dst[6][j] = acc6; dst[7][j] = acc7;
    }
    __syncthreads();

    // ---- P3a: softmax over NS=4 per head (64 threads) ----
    if (t < 64) {
        int tok = t >> 3, hd = t & 7;
        float v0 = logit_sh[tok][hd * 4 + 0] + logit2_sh[tok][hd * 4 + 0];
        float v1 = logit_sh[tok][hd * 4 + 1] + logit2_sh[tok][hd * 4 + 1];
        float v2 = logit_sh[tok][hd * 4 + 2] + logit2_sh[tok][hd * 4 + 2];
        float v3 = logit_sh[tok][hd * 4 + 3] + logit2_sh[tok][hd * 4 + 3];
        float mx = fmaxf(fmaxf(v0, v1), fmaxf(v2, v3));
        float e0 = expf(v0 - mx), e1 = expf(v1 - mx), e2 = expf(v2 - mx), e3 = expf(v3 - mx);
        float inv = 1.0f / (e0 + e1 + e2 + e3);
        aw_sh[tok][hd * 4 + 0] = e0 * inv;
        aw_sh[tok][hd * 4 + 1] = e1 * inv;
        aw_sh[tok][hd * 4 + 2] = e2 * inv;
        aw_sh[tok][hd * 4 + 3] = e3 * inv;
    }
    __syncthreads();

    // ---- P3b: per (tok, q) compute taps + combined weights ----
    {
        int tok = t >> 5, q = lane;
        float rx = ref[((size_t)b * 1024 + p0 + tok) * 2 + 0];
        float ry = ref[((size_t)b * 1024 + p0 + tok) * 2 + 1];
        float lx = logit_sh[tok][32 + 2 * q + 0] + logit2_sh[tok][32 + 2 * q + 0];
        float ly = logit_sh[tok][32 + 2 * q + 1] + logit2_sh[tok][32 + 2 * q + 1];
        float px_ = tanhf(lx) + rx;
        float py_ = tanhf(ly) + ry;
        float fw = (float)(W - 1);
        float gx = fminf(fmaxf((px_ + 1.0f) * 0.5f * fw, 0.0f), fw);
        float gy = fminf(fmaxf((py_ + 1.0f) * 0.5f * fw, 0.0f), fw);
        float x0f = floorf(gx), y0f = floorf(gy);
        float wx = gx - x0f, wy = gy - y0f;
        int x0i = (int)x0f, y0i = (int)y0f;
        int x1i = min(x0i + 1, W - 1), y1i = min(y0i + 1, W - 1);
        *(int4*)tap_sh[tok][q] = make_int4((y0i * W + x0i) * 32, (y0i * W + x1i) * 32,
                                           (y1i * W + x0i) * 32, (y1i * W + x1i) * 32);
        float a = aw_sh[tok][q];
        *(float4*)wgt_sh[tok][q] = make_float4(a * (1.0f - wx) * (1.0f - wy),
                                               a * wx * (1.0f - wy),
                                               a * (1.0f - wx) * wy,
                                               a * wx * wy);
    }
    __syncthreads();

    // ---- P4: coalesced gather + head accumulate ----
#pragma unroll
    for (int iter = 0; iter < 2; iter++) {
        int slot = t + 256 * iter;           // 0..511
        int tok = slot >> 6;
        int head = (slot >> 3) & 7;
        int cg = (slot & 7) * 4;
        float ax = 0.0f, ay = 0.0f, az = 0.0f, aw4 = 0.0f;
#pragma unroll
        for (int s = 0; s < 4; s++) {
            int q = head * 4 + s;
            int4 tp = *(const int4*)tap_sh[tok][q];
            float4 wt = *(const float4*)wgt_sh[tok][q];
            float4 f0 = *(const float4*)(lvlbase + tp.x + cg);
            float4 f1 = *(const float4*)(lvlbase + tp.y + cg);
            float4 f2 = *(const float4*)(lvlbase + tp.z + cg);
            float4 f3 = *(const float4*)(lvlbase + tp.w + cg);
            ax = fmaf(wt.x, f0.x, fmaf(wt.y, f1.x, fmaf(wt.z, f2.x, fmaf(wt.w, f3.x, ax))));
            ay = fmaf(wt.x, f0.y, fmaf(wt.y, f1.y, fmaf(wt.z, f2.y, fmaf(wt.w, f3.y, ay))));
            az = fmaf(wt.x, f0.z, fmaf(wt.y, f1.z, fmaf(wt.z, f2.z, fmaf(wt.w, f3.z, az))));
            aw4 = fmaf(wt.x, f0.w, fmaf(wt.y, f1.w, fmaf(wt.z, f2.w, fmaf(wt.w, f3.w, aw4))));
        }
        *(float4*)&o_sh[tok][head * 32 + cg] = make_float4(ax, ay, az, aw4);
    }
    __syncthreads();

    // ---- P5: residual + LN2 -> bf16 h2 (warp w = token w) ----
    {
        size_t xq_off = base_q + (size_t)w * 256;
        float o8[8];
        float s = 0.0f;
#pragma unroll
        for (int i = 0; i < 8; i++) {
            int c = lane + 32 * i;
            float xq2 = x[xq_off + c] + o_sh[w][c];
            out[xq_off + c] = xq2;
            o8[i] = xq2;
            s += xq2;
        }
#pragma unroll
        for (int o = 16; o > 0; o >>= 1) s += __shfl_xor_sync(0xffffffffu, s, o);
        float mean = s * (1.0f / 256.0f);
        float v = 0.0f;
#pragma unroll
        for (int i = 0; i < 8; i++) { float d = o8[i] - mean; v += d * d; }
#pragma unroll
        for (int o = 16; o > 0; o >>= 1) v += __shfl_xor_sync(0xffffffffu, v, o);
        float rstd = rsqrtf(v * (1.0f / 256.0f) + 1e-5f);
#pragma unroll
        for (int i = 0; i < 8; i++) {
            int c = lane + 32 * i;
            g_h2b[(size_t)(m0 + w) * 256 + c] =
                __float2bfloat16((o8[i] - mean) * rstd * n2g[c] + n2b[c]);
        }
    }
}

// ---------------- bf16 tensor-core GEMM (m16n8k16, fp32 accumulate) ----------------
// A bf16 row-major; B pre-packed fragment-ready (uint4 per lane per nt-pair).
template <int K, int NDIM, int EPI>
__global__ __launch_bounds__(256, 2) void mma_gemm(const float* __restrict__ bias,
                                                   float* __restrict__ out) {
    const unsigned* A = (EPI == 0) ? (const unsigned*)g_h2b : (const unsigned*)g_mlpb;
    const uint4* Bpk = (EPI == 0) ? (const uint4*)g_w1 : (const uint4*)g_w2;
    const int KW = K / 2;
    const int GG = NDIM / 16;           // total column-group-pairs

    __shared__ unsigned As[2][128][12];
    __shared__ __align__(16) uint4 Bs[2][8][32];

    int tid = threadIdx.x;
    int m0 = blockIdx.y * 128, n0 = blockIdx.x * 128;

    int aRow = tid >> 1, aColP = (tid & 1) * 4;
    const unsigned* Ap = A + (size_t)(m0 + aRow) * KW + aColP;
    int gp = tid >> 5, ln = tid & 31;   // block covers 8 gpairs, 32 lanes
    const uint4* Bp = Bpk + ((size_t)(n0 >> 4) + gp) * 32 + ln;

    int lane = tid & 31, wid = tid >> 5;
    int wm = wid & 3, wn = wid >> 2;
    int gid = lane >> 2, tig = lane & 3;

    float acc[2][8][4];
#pragma unroll
    for (int mt = 0; mt < 2; mt++)
#pragma unroll
        for (int nt = 0; nt < 8; nt++)
#pragma unroll
            for (int r = 0; r < 4; r++) acc[mt][nt][r] = 0.0f;

    uint4 av, bv;
    const int NK = K / 16;

    av = *(const uint4*)Ap;
    bv = Bp[0];
    *(uint4*)&As[0][aRow][aColP] = av;
    Bs[0][gp][ln] = bv;
    __syncthreads();

    for (int ks = 0; ks < NK; ks++) {
        int buf = ks & 1;
        if (ks + 1 < NK) {
            av = *(const uint4*)(Ap + (ks + 1) * 8);
            bv = Bp[(size_t)(ks + 1) * GG * 32];
        }
        {
            unsigned af[2][4];
#pragma unroll
            for (int mt = 0; mt < 2; mt++) {
                int r = wm * 32 + mt * 16 + gid;
                af[mt][0] = As[buf][r][tig];
                af[mt][1] = As[buf][r + 8][tig];
                af[mt][2] = As[buf][r][tig + 4];
                af[mt][3] = As[buf][r + 8][tig + 4];
            }
#pragma unroll
            for (int p = 0; p < 4; p++) {
                uint4 q = Bs[buf][wn * 4 + p][lane];
#pragma unroll
                for (int mt = 0; mt < 2; mt++) {
                    asm volatile(
                        "mma.sync.aligned.m16n8k16.row.col.f32.bf16.bf16.f32 "
                        "{%0,%1,%2,%3},{%4,%5,%6,%7},{%8,%9},{%0,%1,%2,%3};"
                        : "+f"(acc[mt][2 * p][0]), "+f"(acc[mt][2 * p][1]),
                          "+f"(acc[mt][2 * p][2]), "+f"(acc[mt][2 * p][3])
                        : "r"(af[mt][0]), "r"(af[mt][1]), "r"(af[mt][2]), "r"(af[mt][3]),
                          "r"(q.x), "r"(q.y));
                }
#pragma unroll
                for (int mt = 0; mt < 2; mt++) {
                    asm volatile(
                        "mma.sync.aligned.m16n8k16.row.col.f32.bf16.bf16.f32 "
                        "{%0,%1,%2,%3},{%4,%5,%6,%7},{%8,%9},{%0,%1,%2,%3};"
                        : "+f"(acc[mt][2 * p + 1][0]), "+f"(acc[mt][2 * p + 1][1]),
                          "+f"(acc[mt][2 * p + 1][2]), "+f"(acc[mt][2 * p + 1][3])
                        : "r"(af[mt][0]), "r"(af[mt][1]), "r"(af[mt][2]), "r"(af[mt][3]),
                          "r"(q.z), "r"(q.w));
                }
            }
        }
        if (ks + 1 < NK) {
            int nb = (ks + 1) & 1;
            *(uint4*)&As[nb][aRow][aColP] = av;
            Bs[nb][gp][ln] = bv;
        }
        __syncthreads();
    }

#pragma unroll
    for (int mt = 0; mt < 2; mt++) {
#pragma unroll
        for (int nt = 0; nt < 8; nt++) {
            int r0 = m0 + wm * 32 + mt * 16 + gid;
            int c = n0 + wn * 64 + nt * 8 + 2 * tig;
            float bv0 = __ldg(bias + c), bv1 = __ldg(bias + c + 1);
            if (EPI == 0) {
                float v0 = acc[mt][nt][0] + bv0, v1 = acc[mt][nt][1] + bv1;
                float v2 = acc[mt][nt][2] + bv0, v3 = acc[mt][nt][3] + bv1;
                unsigned* gm = (unsigned*)g_mlpb;
                gm[((size_t)r0 * 512 + c) >> 1] = pack_bf2(v0 * normcdff(v0), v1 * normcdff(v1));
                gm[((size_t)(r0 + 8) * 512 + c) >> 1] = pack_bf2(v2 * normcdff(v2), v3 * normcdff(v3));
            } else {
#pragma unroll
                for (int half = 0; half < 2; half++) {
                    int row = r0 + half * 8;
                    int bb = row / 5120;
                    int lpp = row - bb * 5120;
                    int ll = lpp >> 10;
                    int pp = lpp & 1023;
                    float* orow = out + ((size_t)(bb * 6 + ll + 1) * 1024 + pp) * 256 + c;
                    float2 cur = *(float2*)orow;
                    cur.x += acc[mt][nt][half * 2 + 0] + bv0;
                    cur.y += acc[mt][nt][half * 2 + 1] + bv1;
                    *(float2*)orow = cur;
                }
            }
        }
    }
}

// ---------------- launch ----------------
extern "C" void kernel_launch(void* const* d_in, const int* in_sizes, int n_in,
                              void* d_out, int out_size) {
    const float* x    = (const float*)d_in[0];
    const float* ref  = (const float*)d_in[1];
    const float* n1g = (const float*)d_in[7];
    const float* n1b = (const float*)d_in[8];
    const float* awW = (const float*)d_in[9];
    const float* awb = (const float*)d_in[10];
    const float* soW = (const float*)d_in[11];
    const float* sob = (const float*)d_in[12];
    const float* n2g  = (const float*)d_in[23];
    const float* n2b  = (const float*)d_in[24];
    const float* fc1W = (const float*)d_in[25];
    const float* fc1b = (const float*)d_in[26];
    const float* fc2W = (const float*)d_in[27];
    const float* fc2b = (const float*)d_in[28];
    float* out = (float*)d_out;

    ProjParams P;
    for (int lvl = 0; lvl < 5; lvl++) {
        P.feat[lvl] = (const float*)d_in[2 + lvl];
        P.W[lvl]    = (const float*)d_in[13 + 2 * lvl];
        P.bias[lvl] = (const float*)d_in[14 + 2 * lvl];
    }

    convert_w<<<128, 256>>>(fc1W, fc2W);
    proj_all<<<1376, 256>>>(P);
    copy_x0_kernel<<<1024, 256>>>(x, out);
    token_fused<<<2560, 256>>>(x, ref, n1g, n1b, awW, awb, soW, sob, n2g, n2b, out);
    mma_gemm<256, 512, 0><<<dim3(4, 160), 256>>>(fc1b, out);
    mma_gemm<512, 256, 1><<<dim3(2, 160), 256>>>(fc2b, out);
}